// round 12
// baseline (speedup 1.0000x reference)
#include <cuda_runtime.h>
#include <cuda_bf16.h>
#include <cstdint>

// Problem constants
constexpr int Bc  = 4;
constexpr int Sc  = 2048;
constexpr int Dc  = 1024;
constexpr int Hc  = 16;
constexpr int HDc = 64;
constexpr int TD3 = 3 * Dc;          // 3072
constexpr int Mrows = Bc * Sc;       // 8192

// Scratch (device globals; no allocation in kernel_launch)
__device__ float g_attn_fb[(size_t)Bc * Hc * Sc * Sc];
__device__ float g_psum[(size_t)Bc * Hc * Sc * 16];
__device__ __nv_bfloat16 g_x_hi[(size_t)Mrows * Dc],   g_x_lo[(size_t)Mrows * Dc];
__device__ __nv_bfloat16 g_wq_hi[(size_t)TD3 * Dc],    g_wq_lo[(size_t)TD3 * Dc];
__device__ __nv_bfloat16 g_wo_hi[(size_t)Dc * Dc],     g_wo_lo[(size_t)Dc * Dc];
__device__ __nv_bfloat16 g_qkv_hi[(size_t)Mrows * TD3], g_qkv_lo[(size_t)Mrows * TD3];
__device__ __nv_bfloat16 g_v_hi[(size_t)Mrows * Dc],   g_v_lo[(size_t)Mrows * Dc];

// ---------------------------------------------------------------------------
// helpers
// ---------------------------------------------------------------------------
__device__ __forceinline__ uint32_t smem_u32(const void* p) {
    uint32_t a;
    asm("{ .reg .u64 t; cvta.to.shared.u64 t, %1; cvt.u32.u64 %0, t; }"
        : "=r"(a) : "l"(p));
    return a;
}
__device__ __forceinline__ uint32_t sw64(uint32_t o)  { return o ^ ((o >> 3) & 0x30); }
__device__ __forceinline__ uint32_t sw128(uint32_t o) { return o ^ ((o >> 3) & 0x70); }

__device__ __forceinline__ void ldsm4(uint32_t a, uint32_t r[4]) {
    asm volatile("ldmatrix.sync.aligned.m8n8.x4.shared.b16 {%0,%1,%2,%3}, [%4];"
                 : "=r"(r[0]), "=r"(r[1]), "=r"(r[2]), "=r"(r[3]) : "r"(a));
}
__device__ __forceinline__ void ldsm4t(uint32_t a, uint32_t r[4]) {
    asm volatile("ldmatrix.sync.aligned.m8n8.x4.trans.shared.b16 {%0,%1,%2,%3}, [%4];"
                 : "=r"(r[0]), "=r"(r[1]), "=r"(r[2]), "=r"(r[3]) : "r"(a));
}
__device__ __forceinline__ void mma16816(float d[4], const uint32_t a[4], const uint32_t b[2]) {
    asm volatile(
        "mma.sync.aligned.m16n8k16.row.col.f32.bf16.bf16.f32 "
        "{%0,%1,%2,%3}, {%4,%5,%6,%7}, {%8,%9}, {%0,%1,%2,%3};"
        : "+f"(d[0]), "+f"(d[1]), "+f"(d[2]), "+f"(d[3])
        : "r"(a[0]), "r"(a[1]), "r"(a[2]), "r"(a[3]), "r"(b[0]), "r"(b[1]));
}
__device__ __forceinline__ void cp16(uint32_t dst, const void* src) {
    asm volatile("cp.async.cg.shared.global [%0], [%1], 16;" :: "r"(dst), "l"(src));
}
__device__ __forceinline__ void cp_commit() {
    asm volatile("cp.async.commit_group;" ::: "memory");
}
template <int N> __device__ __forceinline__ void cp_wait() {
    asm volatile("cp.async.wait_group %0;" :: "n"(N) : "memory");
}
__device__ __forceinline__ void split_hilo(float4 v, uint2& hw, uint2& lw) {
    __nv_bfloat162 h01 = __floats2bfloat162_rn(v.x, v.y);
    __nv_bfloat162 h23 = __floats2bfloat162_rn(v.z, v.w);
    float r0 = v.x - __low2float(h01);
    float r1 = v.y - __high2float(h01);
    float r2 = v.z - __low2float(h23);
    float r3 = v.w - __high2float(h23);
    __nv_bfloat162 l01 = __floats2bfloat162_rn(r0, r1);
    __nv_bfloat162 l23 = __floats2bfloat162_rn(r2, r3);
    hw.x = *reinterpret_cast<uint32_t*>(&h01); hw.y = *reinterpret_cast<uint32_t*>(&h23);
    lw.x = *reinterpret_cast<uint32_t*>(&l01); lw.y = *reinterpret_cast<uint32_t*>(&l23);
}
__device__ __forceinline__ void pack_hilo(float v0, float v1, uint32_t& h, uint32_t& l) {
    __nv_bfloat162 h2 = __floats2bfloat162_rn(v0, v1);
    float r0 = v0 - __low2float(h2), r1 = v1 - __high2float(h2);
    __nv_bfloat162 l2 = __floats2bfloat162_rn(r0, r1);
    h = *reinterpret_cast<uint32_t*>(&h2);
    l = *reinterpret_cast<uint32_t*>(&l2);
}
// exp(s/8) via 2^(s*0.125*log2e), degree-6 poly + exponent splice (FMA pipe).
__device__ __forceinline__ float fexp8(float s) {
    float v = s * 0.1803368801111244f;   // 0.125 * log2(e)
    float fl = floorf(v);
    float f = v - fl;
    float p = 1.5435906e-4f;
    p = fmaf(p, f, 1.3333558e-3f);
    p = fmaf(p, f, 9.6181291e-3f);
    p = fmaf(p, f, 5.5504109e-2f);
    p = fmaf(p, f, 2.4022651e-1f);
    p = fmaf(p, f, 6.9314718e-1f);
    p = fmaf(p, f, 1.0f);
    return __int_as_float(__float_as_int(p) + ((int)fl << 23));
}

// ---------------------------------------------------------------------------
// merged convert kernel: three fp32 -> (hi, lo) arrays in one launch
// ---------------------------------------------------------------------------
__global__ __launch_bounds__(256) void cvt_hilo3(
    const float4* __restrict__ in0, uint2* __restrict__ h0, uint2* __restrict__ l0,
    const float4* __restrict__ in1, uint2* __restrict__ h1, uint2* __restrict__ l1,
    const float4* __restrict__ in2, uint2* __restrict__ h2, uint2* __restrict__ l2)
{
    const int bx = blockIdx.x;
    const float4* in; uint2 *hp, *lp; int i;
    if (bx < 8192)       { in = in0; hp = h0; lp = l0; i = bx * 256 + threadIdx.x; }
    else if (bx < 11264) { in = in1; hp = h1; lp = l1; i = (bx - 8192) * 256 + threadIdx.x; }
    else                 { in = in2; hp = h2; lp = l2; i = (bx - 11264) * 256 + threadIdx.x; }
    uint2 h, l;
    split_hilo(in[i], h, l);
    hp[i] = h; lp[i] = l;
}

// ---------------------------------------------------------------------------
// compute core: one BK=32 chunk; A,B tiles 128 rows x 64B, SW64
// ---------------------------------------------------------------------------
__device__ __forceinline__ void compute64(uint32_t sb, int wm, int wn, int lane,
                                          float acc[2][8][4]) {
    const uint32_t Ah = sb, Al = sb + 8192, Bh = sb + 16384, Bl = sb + 24576;
    const int arow = ((lane >> 3) & 1) * 8 + (lane & 7);
    const int brow = ((lane >> 4) & 1) * 8 + (lane & 7);
#pragma unroll
    for (int ks = 0; ks < 2; ks++) {
        const uint32_t akb = (uint32_t)(ks * 32 + ((lane >> 4) & 1) * 16);
        const uint32_t bkb = (uint32_t)(ks * 32 + ((lane >> 3) & 1) * 16);
        uint32_t ah[2][4], al[2][4];
#pragma unroll
        for (int mt = 0; mt < 2; mt++) {
            const uint32_t off = sw64((uint32_t)(wm + mt * 16 + arow) * 64 + akb);
            ldsm4(Ah + off, ah[mt]);
            ldsm4(Al + off, al[mt]);
        }
#pragma unroll
        for (int half = 0; half < 2; half++) {
            uint32_t bh[4][2], bl[4][2];
#pragma unroll
            for (int p = 0; p < 2; p++) {
                const uint32_t off = sw64((uint32_t)(wn + (half * 2 + p) * 16 + brow) * 64 + bkb);
                uint32_t t[4];
                ldsm4(Bh + off, t);
                bh[2*p][0]=t[0]; bh[2*p][1]=t[1]; bh[2*p+1][0]=t[2]; bh[2*p+1][1]=t[3];
                ldsm4(Bl + off, t);
                bl[2*p][0]=t[0]; bl[2*p][1]=t[1]; bl[2*p+1][0]=t[2]; bl[2*p+1][1]=t[3];
            }
#pragma unroll
            for (int nt = 0; nt < 4; nt++)
#pragma unroll
                for (int mt = 0; mt < 2; mt++) {
                    mma16816(acc[mt][half*4+nt], ah[mt], bh[nt]);
                    mma16816(acc[mt][half*4+nt], ah[mt], bl[nt]);
                    mma16816(acc[mt][half*4+nt], al[mt], bh[nt]);
                }
        }
    }
}

// cp.async one 128x32 bf16 tile (8KB), SW64 rows
__device__ __forceinline__ void cp_tile(uint32_t dst_base, const __nv_bfloat16* __restrict__ src,
                                        int K, int k0, int tid)
{
#pragma unroll
    for (int i = 0; i < 2; i++) {
        const int id = tid + 256 * i;
        const int row = id >> 2, c16 = id & 3;
        cp16(dst_base + sw64((uint32_t)row * 64 + c16 * 16),
             src + (size_t)row * K + k0 + c16 * 8);
    }
}

// ---------------------------------------------------------------------------
// GEMM: C[128x128] = A @ B^T + bias; 3-stage cp.async, 2 CTAs/SM
// ---------------------------------------------------------------------------
template <bool BF16OUT>
__global__ __launch_bounds__(256, 2) void gemm_bf16(
    const __nv_bfloat16* __restrict__ Ahg, const __nv_bfloat16* __restrict__ Alg,
    const __nv_bfloat16* __restrict__ Bhg, const __nv_bfloat16* __restrict__ Blg,
    int K, float* __restrict__ C, __nv_bfloat16* __restrict__ Chi,
    __nv_bfloat16* __restrict__ Clo, int N, const float* __restrict__ bias)
{
    extern __shared__ uint8_t sm[];
    const uint32_t sb0 = smem_u32(sm);
    const int tid = threadIdx.x, lane = tid & 31, w = tid >> 5;
    const int wm = (w & 3) * 32, wn = (w >> 2) * 64;

    Ahg += (size_t)(blockIdx.y * 128) * K;
    Alg += (size_t)(blockIdx.y * 128) * K;
    Bhg += (size_t)(blockIdx.x * 128) * K;
    Blg += (size_t)(blockIdx.x * 128) * K;

    const int NC = K >> 5;
#pragma unroll 1
    for (int s = 0; s < 2; s++) {
        const uint32_t st = sb0 + (uint32_t)s * 32768;
        cp_tile(st,          Ahg, K, s * 32, tid);
        cp_tile(st + 8192,   Alg, K, s * 32, tid);
        cp_tile(st + 16384,  Bhg, K, s * 32, tid);
        cp_tile(st + 24576,  Blg, K, s * 32, tid);
        cp_commit();
    }

    float acc[2][8][4] = {};
#pragma unroll 1
    for (int c = 0; c < NC; c++) {
        cp_wait<1>();
        __syncthreads();
        if (c + 2 < NC) {
            const uint32_t st = sb0 + (uint32_t)((c + 2) % 3) * 32768;
            cp_tile(st,          Ahg, K, (c + 2) * 32, tid);
            cp_tile(st + 8192,   Alg, K, (c + 2) * 32, tid);
            cp_tile(st + 16384,  Bhg, K, (c + 2) * 32, tid);
            cp_tile(st + 24576,  Blg, K, (c + 2) * 32, tid);
        }
        cp_commit();
        compute64(sb0 + (uint32_t)(c % 3) * 32768, wm, wn, lane, acc);
    }

    const int gr = blockIdx.y * 128 + wm + (lane >> 2);
    const int gc = blockIdx.x * 128 + wn + (lane & 3) * 2;
#pragma unroll
    for (int mt = 0; mt < 2; mt++) {
        const int r0 = gr + mt * 16;
#pragma unroll
        for (int nt = 0; nt < 8; nt++) {
            const int cc = gc + nt * 8;
            const float b0 = __ldg(bias + cc), b1 = __ldg(bias + cc + 1);
            const float v00 = acc[mt][nt][0] + b0, v01 = acc[mt][nt][1] + b1;
            const float v10 = acc[mt][nt][2] + b0, v11 = acc[mt][nt][3] + b1;
            if (BF16OUT) {
                uint32_t h, l;
                pack_hilo(v00, v01, h, l);
                *reinterpret_cast<uint32_t*>(Chi + (size_t)r0 * N + cc) = h;
                *reinterpret_cast<uint32_t*>(Clo + (size_t)r0 * N + cc) = l;
                pack_hilo(v10, v11, h, l);
                *reinterpret_cast<uint32_t*>(Chi + (size_t)(r0 + 8) * N + cc) = h;
                *reinterpret_cast<uint32_t*>(Clo + (size_t)(r0 + 8) * N + cc) = l;
            } else {
                float2 u0 = {v00, v01}, u1 = {v10, v11};
                *reinterpret_cast<float2*>(C + (size_t)r0 * N + cc) = u0;
                *reinterpret_cast<float2*>(C + (size_t)(r0 + 8) * N + cc) = u1;
            }
        }
    }
}

// ---------------------------------------------------------------------------
// Scores: attn = exp((Q.K^T)/8) (unnormalized) + per-tile row sums.
// Row sums via in-register accumulation + quad shuffles (no serial LDS loop).
// smem: 64KB fp32 staging + 1KB row-sum partials @65536
// ---------------------------------------------------------------------------
__global__ __launch_bounds__(256, 2) void scores_mma(
    const __nv_bfloat16* __restrict__ qh, const __nv_bfloat16* __restrict__ ql,
    float* __restrict__ attn, float* __restrict__ psum)
{
    extern __shared__ uint8_t sm[];
    const uint32_t sb0 = smem_u32(sm);
    const int tid = threadIdx.x, lane = tid & 31, w = tid >> 5;
    const int wm = (w & 3) * 32, wn = (w >> 2) * 64;
    const int z = blockIdx.z, b = z >> 4, h = z & 15;
    const size_t hb = (size_t)b * Sc * TD3 + h * 192;
    const __nv_bfloat16* Qh = qh + hb + (size_t)(blockIdx.y * 128) * TD3;
    const __nv_bfloat16* Ql = ql + hb + (size_t)(blockIdx.y * 128) * TD3;
    const __nv_bfloat16* Kh = qh + hb + 64 + (size_t)(blockIdx.x * 128) * TD3;
    const __nv_bfloat16* Kl = ql + hb + 64 + (size_t)(blockIdx.x * 128) * TD3;

#pragma unroll
    for (int i = 0; i < 4; i++) {
        const int id = tid + 256 * i;
        const int row = id >> 3, c16 = id & 7;
        const uint32_t d = sw128((uint32_t)row * 128 + c16 * 16);
        const size_t so = (size_t)row * TD3 + c16 * 8;
        cp16(sb0 +         d, Qh + so);
        cp16(sb0 + 16384 + d, Ql + so);
        cp16(sb0 + 32768 + d, Kh + so);
        cp16(sb0 + 49152 + d, Kl + so);
    }
    cp_commit();
    cp_wait<0>();
    __syncthreads();

    float acc[2][8][4] = {};
    {
        const uint32_t Ah = sb0, Al = sb0 + 16384, Bh = sb0 + 32768, Bl = sb0 + 49152;
        const int arow = ((lane >> 3) & 1) * 8 + (lane & 7);
        const int brow = ((lane >> 4) & 1) * 8 + (lane & 7);
#pragma unroll
        for (int ks = 0; ks < 4; ks++) {
            const uint32_t akb = (uint32_t)(ks * 32 + ((lane >> 4) & 1) * 16);
            const uint32_t bkb = (uint32_t)(ks * 32 + ((lane >> 3) & 1) * 16);
            uint32_t ah[2][4], al[2][4];
#pragma unroll
            for (int mt = 0; mt < 2; mt++) {
                const uint32_t off = sw128((uint32_t)(wm + mt * 16 + arow) * 128 + akb);
                ldsm4(Ah + off, ah[mt]);
                ldsm4(Al + off, al[mt]);
            }
#pragma unroll
            for (int half = 0; half < 2; half++) {
                uint32_t bh[4][2], bl[4][2];
#pragma unroll
                for (int p = 0; p < 2; p++) {
                    const uint32_t off = sw128((uint32_t)(wn + (half * 2 + p) * 16 + brow) * 128 + bkb);
                    uint32_t t[4];
                    ldsm4(Bh + off, t);
                    bh[2*p][0]=t[0]; bh[2*p][1]=t[1]; bh[2*p+1][0]=t[2]; bh[2*p+1][1]=t[3];
                    ldsm4(Bl + off, t);
                    bl[2*p][0]=t[0]; bl[2*p][1]=t[1]; bl[2*p+1][0]=t[2]; bl[2*p+1][1]=t[3];
                }
#pragma unroll
                for (int nt = 0; nt < 4; nt++)
#pragma unroll
                    for (int mt = 0; mt < 2; mt++) {
                        mma16816(acc[mt][half*4+nt], ah[mt], bh[nt]);
                        mma16816(acc[mt][half*4+nt], ah[mt], bl[nt]);
                        mma16816(acc[mt][half*4+nt], al[mt], bh[nt]);
                    }
            }
        }
    }
    __syncthreads();

    // exp (FMA-pipe poly) to fp32 smem staging + register row-sum accumulation
    float* smf = reinterpret_cast<float*>(sm);
    float* smp = reinterpret_cast<float*>(sm + 65536);  // [128 rows][2 colgroups]
    const int r0 = wm + (lane >> 2);
    const int c0 = wn + (lane & 3) * 2;
    float rs[2][2] = {{0.f, 0.f}, {0.f, 0.f}};
#pragma unroll
    for (int mt = 0; mt < 2; mt++) {
#pragma unroll
        for (int nt = 0; nt < 8; nt++) {
            const int cc = c0 + nt * 8;
            const float e0 = fexp8(acc[mt][nt][0]);
            const float e1 = fexp8(acc[mt][nt][1]);
            const float e2 = fexp8(acc[mt][nt][2]);
            const float e3 = fexp8(acc[mt][nt][3]);
            smf[(r0 + mt * 16) * 128 + cc]     = e0;
            smf[(r0 + mt * 16) * 128 + cc + 1] = e1;
            smf[(r0 + mt * 16 + 8) * 128 + cc]     = e2;
            smf[(r0 + mt * 16 + 8) * 128 + cc + 1] = e3;
            rs[mt][0] += e0 + e1;
            rs[mt][1] += e2 + e3;
        }
    }
#pragma unroll
    for (int mt = 0; mt < 2; mt++)
#pragma unroll
        for (int hh = 0; hh < 2; hh++) {
            float s = rs[mt][hh];
            s += __shfl_xor_sync(0xFFFFFFFFu, s, 1);
            s += __shfl_xor_sync(0xFFFFFFFFu, s, 2);
            if ((lane & 3) == 0)
                smp[(wm + mt * 16 + hh * 8 + (lane >> 2)) * 2 + (w >> 2)] = s;
        }
    __syncthreads();

    if (tid < 128)
        psum[((size_t)z * Sc + blockIdx.y * 128 + tid) * 16 + blockIdx.x]
            = smp[tid * 2] + smp[tid * 2 + 1];

    float* cbase = attn + (size_t)z * Sc * Sc + (size_t)(blockIdx.y * 128) * Sc
                 + blockIdx.x * 128;
    const float4* s4 = reinterpret_cast<const float4*>(sm);
#pragma unroll
    for (int i = 0; i < 16; i++) {
        const int id = tid + 256 * i;
        const int row = id >> 5, u = id & 31;
        *reinterpret_cast<float4*>(cbase + (size_t)row * Sc + u * 4) = s4[id];
    }
}

// ---------------------------------------------------------------------------
// PV: 3-deep async pipeline (A fp32 staging + V), paired A/V commit groups.
// smem: A staging 3x16KB @0 ; A bf16 MMA bufs 2x16KB @49152 ;
//       V bf16 3x8KB @81920 ; invs @106496
// ---------------------------------------------------------------------------
constexpr uint32_t PV_AST = 0;
constexpr uint32_t PV_AB  = 49152;
constexpr uint32_t PV_V   = 81920;
constexpr uint32_t PV_INV = 106496;
constexpr uint32_t PV_SMEM = 107008;

__device__ __forceinline__ void computePV(uint32_t ab, uint32_t vb, int wm, int wn, int lane,
                                          float acc[2][4][4]) {
    const uint32_t Ah = ab, Al = ab + 8192, Vh = vb, Vl = vb + 4096;
    const int arow = ((lane >> 3) & 1) * 8 + (lane & 7);
    const int krw  = ((lane >> 3) & 1) * 8 + (lane & 7);
    const int dof  = ((lane >> 4) & 1) * 8;
#pragma unroll
    for (int ks = 0; ks < 2; ks++) {
        const uint32_t akb = (uint32_t)(ks * 32 + ((lane >> 4) & 1) * 16);
        uint32_t ah[2][4], al[2][4];
#pragma unroll
        for (int mt = 0; mt < 2; mt++) {
            const uint32_t off = sw64((uint32_t)(wm + mt * 16 + arow) * 64 + akb);
            ldsm4(Ah + off, ah[mt]);
            ldsm4(Al + off, al[mt]);
        }
        uint32_t vh[4][2], vl[4][2];
#pragma unroll
        for (int p = 0; p < 2; p++) {
            const uint32_t off = sw128((uint32_t)(ks * 16 + krw) * 128 +
                                       (uint32_t)(wn + p * 16 + dof) * 2);
            uint32_t t[4];
            ldsm4t(Vh + off, t);
            vh[2*p][0]=t[0]; vh[2*p][1]=t[1]; vh[2*p+1][0]=t[2]; vh[2*p+1][1]=t[3];
            ldsm4t(Vl + off, t);
            vl[2*p][0]=t[0]; vl[2*p][1]=t[1]; vl[2*p+1][0]=t[2]; vl[2*p+1][1]=t[3];
        }
#pragma unroll
        for (int nt = 0; nt < 4; nt++)
#pragma unroll
            for (int mt = 0; mt < 2; mt++) {
                mma16816(acc[mt][nt], ah[mt], vh[nt]);
                mma16816(acc[mt][nt], ah[mt], vl[nt]);
                mma16816(acc[mt][nt], al[mt], vh[nt]);
            }
    }
}

__global__ __launch_bounds__(256, 2) void pv_mma(
    float* __restrict__ attn, const __nv_bfloat16* __restrict__ qh,
    const __nv_bfloat16* __restrict__ ql, const float* __restrict__ psum,
    __nv_bfloat16* __restrict__ voh, __nv_bfloat16* __restrict__ vol)
{
    extern __shared__ uint8_t sm[];
    const uint32_t sb0 = smem_u32(sm);
    float* invs = reinterpret_cast<float*>(sm + PV_INV);
    const int tid = threadIdx.x, lane = tid & 31, w = tid >> 5;
    const int wm = (w & 3) * 32, wn = (w >> 2) * 32;

    const int z = blockIdx.y, b = z >> 4, h = z & 15;
    const int qt = blockIdx.x;
    float* A = attn + (size_t)z * Sc * Sc + (size_t)(qt * 128) * Sc;
    const __nv_bfloat16* Vh = qh + (size_t)b * Sc * TD3 + h * 192 + 128;
    const __nv_bfloat16* Vl = ql + (size_t)b * Sc * TD3 + h * 192 + 128;

    // per-thread A region: row = tid>>1, 16 floats at col (tid&1)*16
    const int arow = tid >> 1, acol = (tid & 1) * 16;
    const uint32_t abase = (uint32_t)arow * 128 + (uint32_t)(tid & 1) * 64;
    // V cp mapping
    const int vrow = tid >> 3, vc16 = tid & 7;
    const uint32_t vdst = sw128((uint32_t)vrow * 128 + vc16 * 16);

    // prologue: chunks 0,1,2 — groups ordered A0,V0,A1,V1,A2,V2
#pragma unroll
    for (int s = 0; s < 3; s++) {
        const uint32_t ast = sb0 + PV_AST + (uint32_t)s * 16384;
        const float* asrc = A + (size_t)arow * Sc + s * 32 + acol;
#pragma unroll
        for (int i = 0; i < 4; i++)
            cp16(ast + sw128(abase + i * 16), asrc + i * 4);
        cp_commit();
        const uint32_t vb = sb0 + PV_V + (uint32_t)s * 8192;
        const size_t so = (size_t)(s * 32 + vrow) * TD3 + vc16 * 8;
        cp16(vb + vdst, Vh + so);
        cp16(vb + 4096 + vdst, Vl + so);
        cp_commit();
    }
    if (tid < 128) {
        const float* pp = psum + ((size_t)z * Sc + qt * 128 + tid) * 16;
        float s = 0.f;
#pragma unroll
        for (int j = 0; j < 16; j++) s += pp[j];
        invs[tid] = 1.f / s;
    }
    __syncthreads();
    const float inv = invs[arow];

    float acc[2][4][4] = {};
#pragma unroll 1
    for (int c = 0; c < 64; c++) {
        cp_wait<4>();   // A(c) and V(c) arrived (4 newer groups may be pending)
        const uint32_t ast = sb0 + PV_AST + (uint32_t)(c % 3) * 16384;
        const uint32_t ab  = sb0 + PV_AB  + (uint32_t)(c & 1) * 16384;
        // consume own staging region: scale, STG normalized, pack bf16
        float* aout = A + (size_t)arow * Sc + c * 32 + acol;
#pragma unroll
        for (int i = 0; i < 4; i++) {
            float4 v = *reinterpret_cast<const float4*>(sm + (ast - sb0) + sw128(abase + i * 16));
            v.x *= inv; v.y *= inv; v.z *= inv; v.w *= inv;
            *reinterpret_cast<float4*>(aout + i * 4) = v;
            uint2 hw, lw;
            split_hilo(v, hw, lw);
            const uint32_t swo = sw64(abase / 2 + i * 8);
            *reinterpret_cast<uint2*>(sm + (ab - sb0) + swo) = hw;
            *reinterpret_cast<uint2*>(sm + (ab - sb0) + 8192 + swo) = lw;
        }
        // prefetch A(c+3) into staging slot c%3 (own region just consumed)
        if (c + 3 < 64) {
            const float* asrc = A + (size_t)arow * Sc + (c + 3) * 32 + acol;
#pragma unroll
            for (int i = 0; i < 4; i++)
                cp16(ast + sw128(abase + i * 16), asrc + i * 4);
        }
        cp_commit();
        __syncthreads();
        computePV(ab, sb0 + PV_V + (uint32_t)(c % 3) * 8192, wm, wn, lane, acc);
        __syncthreads();
        // prefetch V(c+3) into V slot c%3 (all readers done per sync above)
        if (c + 3 < 64) {
            const uint32_t vb = sb0 + PV_V + (uint32_t)(c % 3) * 8192;
            const size_t so = (size_t)((c + 3) * 32 + vrow) * TD3 + vc16 * 8;
            cp16(vb + vdst, Vh + so);
            cp16(vb + 4096 + vdst, Vl + so);
        }
        cp_commit();
    }

    __nv_bfloat16* Oh = voh + (size_t)z * Sc * HDc + (size_t)(qt * 128) * HDc;
    __nv_bfloat16* Ol = vol + (size_t)z * Sc * HDc + (size_t)(qt * 128) * HDc;
    const int r0b = wm + (lane >> 2);
    const int ccb = wn + (lane & 3) * 2;
#pragma unroll
    for (int mt = 0; mt < 2; mt++) {
        const int r0 = r0b + mt * 16;
#pragma unroll
        for (int nt = 0; nt < 4; nt++) {
            const int cc = ccb + nt * 8;
            uint32_t hh, ll;
            pack_hilo(acc[mt][nt][0], acc[mt][nt][1], hh, ll);
            *reinterpret_cast<uint32_t*>(Oh + (size_t)r0 * HDc + cc) = hh;
            *reinterpret_cast<uint32_t*>(Ol + (size_t)r0 * HDc + cc) = ll;
            pack_hilo(acc[mt][nt][2], acc[mt][nt][3], hh, ll);
            *reinterpret_cast<uint32_t*>(Oh + (size_t)(r0 + 8) * HDc + cc) = hh;
            *reinterpret_cast<uint32_t*>(Ol + (size_t)(r0 + 8) * HDc + cc) = ll;
        }
    }
}

// ---------------------------------------------------------------------------
extern "C" void kernel_launch(void* const* d_in, const int* in_sizes, int n_in,
                              void* d_out, int out_size)
{
    const float* x     = (const float*)d_in[0];
    const float* w_qkv = (const float*)d_in[1];
    const float* b_qkv = (const float*)d_in[2];
    const float* w_out = (const float*)d_in[3];
    const float* b_out = (const float*)d_in[4];
    float* out = (float*)d_out;

    const size_t BSD  = (size_t)Bc * Sc * Dc;
    const size_t BHSS = (size_t)Bc * Hc * Sc * Sc;

    float *attn_fb, *psum;
    cudaGetSymbolAddress((void**)&attn_fb, g_attn_fb);
    cudaGetSymbolAddress((void**)&psum,    g_psum);
    __nv_bfloat16 *xh, *xl, *wqh, *wql, *woh, *wol, *qkvh, *qkvl, *vh, *vl;
    cudaGetSymbolAddress((void**)&xh,   g_x_hi);   cudaGetSymbolAddress((void**)&xl,   g_x_lo);
    cudaGetSymbolAddress((void**)&wqh,  g_wq_hi);  cudaGetSymbolAddress((void**)&wql,  g_wq_lo);
    cudaGetSymbolAddress((void**)&woh,  g_wo_hi);  cudaGetSymbolAddress((void**)&wol,  g_wo_lo);
    cudaGetSymbolAddress((void**)&qkvh, g_qkv_hi); cudaGetSymbolAddress((void**)&qkvl, g_qkv_lo);
    cudaGetSymbolAddress((void**)&vh,   g_v_hi);   cudaGetSymbolAddress((void**)&vl,   g_v_lo);

    float* attn = ((size_t)out_size >= BSD + BHSS) ? (out + BSD) : attn_fb;

    cudaFuncSetAttribute(gemm_bf16<true>,  cudaFuncAttributeMaxDynamicSharedMemorySize, 98304);
    cudaFuncSetAttribute(gemm_bf16<false>, cudaFuncAttributeMaxDynamicSharedMemorySize, 98304);
    cudaFuncSetAttribute(scores_mma,       cudaFuncAttributeMaxDynamicSharedMemorySize, 66560);
    cudaFuncSetAttribute(pv_mma,           cudaFuncAttributeMaxDynamicSharedMemorySize, PV_SMEM);

    // 0) pre-split fp32 -> bf16 hi/lo
    cvt_hilo3<<<12288, 256>>>(
        (const float4*)x,     (uint2*)xh,  (uint2*)xl,
        (const float4*)w_qkv, (uint2*)wqh, (uint2*)wql,
        (const float4*)w_out, (uint2*)woh, (uint2*)wol);

    // 1) fused QKV projection -> bf16 hi/lo qkv
    gemm_bf16<true><<<dim3(TD3 / 128, Mrows / 128), 256, 98304>>>(
        xh, xl, wqh, wql, Dc, nullptr, qkvh, qkvl, TD3, b_qkv);

    // 2) scores: exp(QK/8) + per-tile row sums
    scores_mma<<<dim3(Sc / 128, Sc / 128, Bc * Hc), 256, 66560>>>(qkvh, qkvl, attn, psum);

    // 3) PV: normalize attn in place + vals = attn_norm @ V (writes vals hi/lo)
    pv_mma<<<dim3(Sc / 128, Bc * Hc), 256, PV_SMEM>>>(attn, qkvh, qkvl, psum, vh, vl);

    // 4) output projection
    gemm_bf16<false><<<dim3(Dc / 128, Mrows / 128), 256, 98304>>>(
        vh, vl, woh, wol, Dc, out, nullptr, nullptr, Dc, b_out);
}

// round 13
// speedup vs baseline: 1.0618x; 1.0618x over previous
#include <cuda_runtime.h>
#include <cuda_bf16.h>
#include <cstdint>

// Problem constants
constexpr int Bc  = 4;
constexpr int Sc  = 2048;
constexpr int Dc  = 1024;
constexpr int Hc  = 16;
constexpr int HDc = 64;
constexpr int TD3 = 3 * Dc;          // 3072
constexpr int Mrows = Bc * Sc;       // 8192

// Scratch (device globals; no allocation in kernel_launch)
__device__ float g_attn_fb[(size_t)Bc * Hc * Sc * Sc];
__device__ __nv_bfloat16 g_x_hi[(size_t)Mrows * Dc],   g_x_lo[(size_t)Mrows * Dc];
__device__ __nv_bfloat16 g_wq_hi[(size_t)TD3 * Dc],    g_wq_lo[(size_t)TD3 * Dc];
__device__ __nv_bfloat16 g_wo_hi[(size_t)Dc * Dc],     g_wo_lo[(size_t)Dc * Dc];
__device__ __nv_bfloat16 g_qkv_hi[(size_t)Mrows * TD3], g_qkv_lo[(size_t)Mrows * TD3];
__device__ __nv_bfloat16 g_v_hi[(size_t)Mrows * Dc],   g_v_lo[(size_t)Mrows * Dc];

// ---------------------------------------------------------------------------
// helpers
// ---------------------------------------------------------------------------
__device__ __forceinline__ uint32_t smem_u32(const void* p) {
    uint32_t a;
    asm("{ .reg .u64 t; cvta.to.shared.u64 t, %1; cvt.u32.u64 %0, t; }"
        : "=r"(a) : "l"(p));
    return a;
}
__device__ __forceinline__ uint32_t sw64(uint32_t o)  { return o ^ ((o >> 3) & 0x30); }
__device__ __forceinline__ uint32_t sw128(uint32_t o) { return o ^ ((o >> 3) & 0x70); }

__device__ __forceinline__ void ldsm4(uint32_t a, uint32_t r[4]) {
    asm volatile("ldmatrix.sync.aligned.m8n8.x4.shared.b16 {%0,%1,%2,%3}, [%4];"
                 : "=r"(r[0]), "=r"(r[1]), "=r"(r[2]), "=r"(r[3]) : "r"(a));
}
__device__ __forceinline__ void ldsm4t(uint32_t a, uint32_t r[4]) {
    asm volatile("ldmatrix.sync.aligned.m8n8.x4.trans.shared.b16 {%0,%1,%2,%3}, [%4];"
                 : "=r"(r[0]), "=r"(r[1]), "=r"(r[2]), "=r"(r[3]) : "r"(a));
}
__device__ __forceinline__ void mma16816(float d[4], const uint32_t a[4], const uint32_t b[2]) {
    asm volatile(
        "mma.sync.aligned.m16n8k16.row.col.f32.bf16.bf16.f32 "
        "{%0,%1,%2,%3}, {%4,%5,%6,%7}, {%8,%9}, {%0,%1,%2,%3};"
        : "+f"(d[0]), "+f"(d[1]), "+f"(d[2]), "+f"(d[3])
        : "r"(a[0]), "r"(a[1]), "r"(a[2]), "r"(a[3]), "r"(b[0]), "r"(b[1]));
}
__device__ __forceinline__ void cp16(uint32_t dst, const void* src) {
    asm volatile("cp.async.cg.shared.global [%0], [%1], 16;" :: "r"(dst), "l"(src));
}
__device__ __forceinline__ void cp_commit() {
    asm volatile("cp.async.commit_group;" ::: "memory");
}
template <int N> __device__ __forceinline__ void cp_wait() {
    asm volatile("cp.async.wait_group %0;" :: "n"(N) : "memory");
}
__device__ __forceinline__ void split_hilo(float4 v, uint2& hw, uint2& lw) {
    __nv_bfloat162 h01 = __floats2bfloat162_rn(v.x, v.y);
    __nv_bfloat162 h23 = __floats2bfloat162_rn(v.z, v.w);
    float r0 = v.x - __low2float(h01);
    float r1 = v.y - __high2float(h01);
    float r2 = v.z - __low2float(h23);
    float r3 = v.w - __high2float(h23);
    __nv_bfloat162 l01 = __floats2bfloat162_rn(r0, r1);
    __nv_bfloat162 l23 = __floats2bfloat162_rn(r2, r3);
    hw.x = *reinterpret_cast<uint32_t*>(&h01); hw.y = *reinterpret_cast<uint32_t*>(&h23);
    lw.x = *reinterpret_cast<uint32_t*>(&l01); lw.y = *reinterpret_cast<uint32_t*>(&l23);
}
__device__ __forceinline__ void pack_hilo(float v0, float v1, uint32_t& h, uint32_t& l) {
    __nv_bfloat162 h2 = __floats2bfloat162_rn(v0, v1);
    float r0 = v0 - __low2float(h2), r1 = v1 - __high2float(h2);
    __nv_bfloat162 l2 = __floats2bfloat162_rn(r0, r1);
    h = *reinterpret_cast<uint32_t*>(&h2);
    l = *reinterpret_cast<uint32_t*>(&l2);
}
// exp(s/8) via 2^(s*0.125*log2e), degree-6 poly + exponent splice (FMA pipe).
__device__ __forceinline__ float fexp8(float s) {
    float v = s * 0.1803368801111244f;   // 0.125 * log2(e)
    float fl = floorf(v);
    float f = v - fl;
    float p = 1.5435906e-4f;
    p = fmaf(p, f, 1.3333558e-3f);
    p = fmaf(p, f, 9.6181291e-3f);
    p = fmaf(p, f, 5.5504109e-2f);
    p = fmaf(p, f, 2.4022651e-1f);
    p = fmaf(p, f, 6.9314718e-1f);
    p = fmaf(p, f, 1.0f);
    return __int_as_float(__float_as_int(p) + ((int)fl << 23));
}

// ---------------------------------------------------------------------------
// merged convert kernel: three fp32 -> (hi, lo) arrays in one launch
// ---------------------------------------------------------------------------
__global__ __launch_bounds__(256) void cvt_hilo3(
    const float4* __restrict__ in0, uint2* __restrict__ h0, uint2* __restrict__ l0,
    const float4* __restrict__ in1, uint2* __restrict__ h1, uint2* __restrict__ l1,
    const float4* __restrict__ in2, uint2* __restrict__ h2, uint2* __restrict__ l2)
{
    const int bx = blockIdx.x;
    const float4* in; uint2 *hp, *lp; int i;
    if (bx < 8192)       { in = in0; hp = h0; lp = l0; i = bx * 256 + threadIdx.x; }
    else if (bx < 11264) { in = in1; hp = h1; lp = l1; i = (bx - 8192) * 256 + threadIdx.x; }
    else                 { in = in2; hp = h2; lp = l2; i = (bx - 11264) * 256 + threadIdx.x; }
    uint2 h, l;
    split_hilo(in[i], h, l);
    hp[i] = h; lp[i] = l;
}

// ---------------------------------------------------------------------------
// GEMM compute core: one BK=32 chunk; A,B tiles 128 rows x 64B, SW64
// ---------------------------------------------------------------------------
__device__ __forceinline__ void compute64(uint32_t sb, int wm, int wn, int lane,
                                          float acc[2][8][4]) {
    const uint32_t Ah = sb, Al = sb + 8192, Bh = sb + 16384, Bl = sb + 24576;
    const int arow = ((lane >> 3) & 1) * 8 + (lane & 7);
    const int brow = ((lane >> 4) & 1) * 8 + (lane & 7);
#pragma unroll
    for (int ks = 0; ks < 2; ks++) {
        const uint32_t akb = (uint32_t)(ks * 32 + ((lane >> 4) & 1) * 16);
        const uint32_t bkb = (uint32_t)(ks * 32 + ((lane >> 3) & 1) * 16);
        uint32_t ah[2][4], al[2][4];
#pragma unroll
        for (int mt = 0; mt < 2; mt++) {
            const uint32_t off = sw64((uint32_t)(wm + mt * 16 + arow) * 64 + akb);
            ldsm4(Ah + off, ah[mt]);
            ldsm4(Al + off, al[mt]);
        }
#pragma unroll
        for (int half = 0; half < 2; half++) {
            uint32_t bh[4][2], bl[4][2];
#pragma unroll
            for (int p = 0; p < 2; p++) {
                const uint32_t off = sw64((uint32_t)(wn + (half * 2 + p) * 16 + brow) * 64 + bkb);
                uint32_t t[4];
                ldsm4(Bh + off, t);
                bh[2*p][0]=t[0]; bh[2*p][1]=t[1]; bh[2*p+1][0]=t[2]; bh[2*p+1][1]=t[3];
                ldsm4(Bl + off, t);
                bl[2*p][0]=t[0]; bl[2*p][1]=t[1]; bl[2*p+1][0]=t[2]; bl[2*p+1][1]=t[3];
            }
#pragma unroll
            for (int nt = 0; nt < 4; nt++)
#pragma unroll
                for (int mt = 0; mt < 2; mt++) {
                    mma16816(acc[mt][half*4+nt], ah[mt], bh[nt]);
                    mma16816(acc[mt][half*4+nt], ah[mt], bl[nt]);
                    mma16816(acc[mt][half*4+nt], al[mt], bh[nt]);
                }
        }
    }
}

// cp.async one 128x32 bf16 tile (8KB), SW64 rows
__device__ __forceinline__ void cp_tile(uint32_t dst_base, const __nv_bfloat16* __restrict__ src,
                                        int K, int k0, int tid)
{
#pragma unroll
    for (int i = 0; i < 2; i++) {
        const int id = tid + 256 * i;
        const int row = id >> 2, c16 = id & 3;
        cp16(dst_base + sw64((uint32_t)row * 64 + c16 * 16),
             src + (size_t)row * K + k0 + c16 * 8);
    }
}

// ---------------------------------------------------------------------------
// GEMM: C[128x128] = A @ B^T + bias; 3-stage cp.async, 2 CTAs/SM
// ---------------------------------------------------------------------------
template <bool BF16OUT>
__global__ __launch_bounds__(256, 2) void gemm_bf16(
    const __nv_bfloat16* __restrict__ Ahg, const __nv_bfloat16* __restrict__ Alg,
    const __nv_bfloat16* __restrict__ Bhg, const __nv_bfloat16* __restrict__ Blg,
    int K, float* __restrict__ C, __nv_bfloat16* __restrict__ Chi,
    __nv_bfloat16* __restrict__ Clo, int N, const float* __restrict__ bias)
{
    extern __shared__ uint8_t sm[];
    const uint32_t sb0 = smem_u32(sm);
    const int tid = threadIdx.x, lane = tid & 31, w = tid >> 5;
    const int wm = (w & 3) * 32, wn = (w >> 2) * 64;

    Ahg += (size_t)(blockIdx.y * 128) * K;
    Alg += (size_t)(blockIdx.y * 128) * K;
    Bhg += (size_t)(blockIdx.x * 128) * K;
    Blg += (size_t)(blockIdx.x * 128) * K;

    const int NC = K >> 5;
#pragma unroll 1
    for (int s = 0; s < 2; s++) {
        const uint32_t st = sb0 + (uint32_t)s * 32768;
        cp_tile(st,          Ahg, K, s * 32, tid);
        cp_tile(st + 8192,   Alg, K, s * 32, tid);
        cp_tile(st + 16384,  Bhg, K, s * 32, tid);
        cp_tile(st + 24576,  Blg, K, s * 32, tid);
        cp_commit();
    }

    float acc[2][8][4] = {};
#pragma unroll 1
    for (int c = 0; c < NC; c++) {
        cp_wait<1>();
        __syncthreads();
        if (c + 2 < NC) {
            const uint32_t st = sb0 + (uint32_t)((c + 2) % 3) * 32768;
            cp_tile(st,          Ahg, K, (c + 2) * 32, tid);
            cp_tile(st + 8192,   Alg, K, (c + 2) * 32, tid);
            cp_tile(st + 16384,  Bhg, K, (c + 2) * 32, tid);
            cp_tile(st + 24576,  Blg, K, (c + 2) * 32, tid);
        }
        cp_commit();
        compute64(sb0 + (uint32_t)(c % 3) * 32768, wm, wn, lane, acc);
    }

    const int gr = blockIdx.y * 128 + wm + (lane >> 2);
    const int gc = blockIdx.x * 128 + wn + (lane & 3) * 2;
#pragma unroll
    for (int mt = 0; mt < 2; mt++) {
        const int r0 = gr + mt * 16;
#pragma unroll
        for (int nt = 0; nt < 8; nt++) {
            const int cc = gc + nt * 8;
            const float b0 = __ldg(bias + cc), b1 = __ldg(bias + cc + 1);
            const float v00 = acc[mt][nt][0] + b0, v01 = acc[mt][nt][1] + b1;
            const float v10 = acc[mt][nt][2] + b0, v11 = acc[mt][nt][3] + b1;
            if (BF16OUT) {
                uint32_t h, l;
                pack_hilo(v00, v01, h, l);
                *reinterpret_cast<uint32_t*>(Chi + (size_t)r0 * N + cc) = h;
                *reinterpret_cast<uint32_t*>(Clo + (size_t)r0 * N + cc) = l;
                pack_hilo(v10, v11, h, l);
                *reinterpret_cast<uint32_t*>(Chi + (size_t)(r0 + 8) * N + cc) = h;
                *reinterpret_cast<uint32_t*>(Clo + (size_t)(r0 + 8) * N + cc) = l;
            } else {
                float2 u0 = {v00, v01}, u1 = {v10, v11};
                *reinterpret_cast<float2*>(C + (size_t)r0 * N + cc) = u0;
                *reinterpret_cast<float2*>(C + (size_t)(r0 + 8) * N + cc) = u1;
            }
        }
    }
}

// ---------------------------------------------------------------------------
// Fused attention: per (q-tile, z) CTA, Q resident; pass1 computes exp(QK/8)
// into smem S tiles + PV MMA + rowsums (no gmem attn traffic); pass2
// recomputes QK and writes normalized attention once.
// smem layout (bytes):
//   Qh @0 (16K), Ql @16384 (16K)
//   K stages 3 x { hi 4K, lo 4K } @32768
//   V stages 3 x { hi 4K, lo 4K } @57344
//   S tile: hi 8K @81920, lo 8K @90112
//   rsacc[128][2] f32 @98304 ; inv[128] f32 @99328
// ---------------------------------------------------------------------------
constexpr uint32_t FA_Q   = 0;
constexpr uint32_t FA_K   = 32768;
constexpr uint32_t FA_V   = 57344;
constexpr uint32_t FA_S   = 81920;
constexpr uint32_t FA_RS  = 98304;
constexpr uint32_t FA_INV = 99328;
constexpr uint32_t FA_SMEM = 99840;

// QK chunk: S[128 x 32] = Q[128 x 64] . K_chunk[32 x 64]^T, 3-term bf16
__device__ __forceinline__ void computeQK(uint32_t sb0, uint32_t kb, int wm, int wnq,
                                          int lane, float aq[2][2][4]) {
    const uint32_t Qh = sb0 + FA_Q, Ql = sb0 + FA_Q + 16384;
    const uint32_t Kh = kb, Kl = kb + 4096;
    const int arow = ((lane >> 3) & 1) * 8 + (lane & 7);
    const int brow = ((lane >> 4) & 1) * 8 + (lane & 7);
#pragma unroll
    for (int ks = 0; ks < 4; ks++) {
        const uint32_t akb = (uint32_t)(ks * 32 + ((lane >> 4) & 1) * 16);
        const uint32_t bkb = (uint32_t)(ks * 32 + ((lane >> 3) & 1) * 16);
        uint32_t qh[2][4], ql_[2][4];
#pragma unroll
        for (int mt = 0; mt < 2; mt++) {
            const uint32_t off = sw128((uint32_t)(wm + mt * 16 + arow) * 128 + akb);
            ldsm4(Qh + off, qh[mt]);
            ldsm4(Ql + off, ql_[mt]);
        }
        uint32_t bh[2][2], bl[2][2], t[4];
        const uint32_t boff = sw128((uint32_t)(wnq + brow) * 128 + bkb);
        ldsm4(Kh + boff, t);
        bh[0][0]=t[0]; bh[0][1]=t[1]; bh[1][0]=t[2]; bh[1][1]=t[3];
        ldsm4(Kl + boff, t);
        bl[0][0]=t[0]; bl[0][1]=t[1]; bl[1][0]=t[2]; bl[1][1]=t[3];
#pragma unroll
        for (int nt = 0; nt < 2; nt++)
#pragma unroll
            for (int mt = 0; mt < 2; mt++) {
                mma16816(aq[mt][nt], qh[mt], bh[nt]);
                mma16816(aq[mt][nt], qh[mt], bl[nt]);
                mma16816(aq[mt][nt], ql_[mt], bh[nt]);
            }
    }
}

// PV chunk: O += S[128 x 32] . V_chunk[32 x 64]; S SW64, V SW128 trans
__device__ __forceinline__ void computePV(uint32_t ab, uint32_t vb, int wm, int wnp,
                                          int lane, float acc[2][4][4]) {
    const uint32_t Ah = ab, Al = ab + 8192, Vh = vb, Vl = vb + 4096;
    const int arow = ((lane >> 3) & 1) * 8 + (lane & 7);
    const int krw  = ((lane >> 3) & 1) * 8 + (lane & 7);
    const int dof  = ((lane >> 4) & 1) * 8;
#pragma unroll
    for (int ks = 0; ks < 2; ks++) {
        const uint32_t akb = (uint32_t)(ks * 32 + ((lane >> 4) & 1) * 16);
        uint32_t ah[2][4], al[2][4];
#pragma unroll
        for (int mt = 0; mt < 2; mt++) {
            const uint32_t off = sw64((uint32_t)(wm + mt * 16 + arow) * 64 + akb);
            ldsm4(Ah + off, ah[mt]);
            ldsm4(Al + off, al[mt]);
        }
        uint32_t vh[4][2], vl[4][2];
#pragma unroll
        for (int p = 0; p < 2; p++) {
            const uint32_t off = sw128((uint32_t)(ks * 16 + krw) * 128 +
                                       (uint32_t)(wnp + p * 16 + dof) * 2);
            uint32_t t[4];
            ldsm4t(Vh + off, t);
            vh[2*p][0]=t[0]; vh[2*p][1]=t[1]; vh[2*p+1][0]=t[2]; vh[2*p+1][1]=t[3];
            ldsm4t(Vl + off, t);
            vl[2*p][0]=t[0]; vl[2*p][1]=t[1]; vl[2*p+1][0]=t[2]; vl[2*p+1][1]=t[3];
        }
#pragma unroll
        for (int nt = 0; nt < 4; nt++)
#pragma unroll
            for (int mt = 0; mt < 2; mt++) {
                mma16816(acc[mt][nt], ah[mt], vh[nt]);
                mma16816(acc[mt][nt], ah[mt], vl[nt]);
                mma16816(acc[mt][nt], al[mt], vh[nt]);
            }
    }
}

__global__ __launch_bounds__(256, 2) void fused_attn(
    const __nv_bfloat16* __restrict__ qkh, const __nv_bfloat16* __restrict__ qkl,
    float* __restrict__ attn_out,
    __nv_bfloat16* __restrict__ voh, __nv_bfloat16* __restrict__ vol)
{
    extern __shared__ uint8_t sm[];
    const uint32_t sb0 = smem_u32(sm);
    float* rsacc = reinterpret_cast<float*>(sm + FA_RS);
    float* invp  = reinterpret_cast<float*>(sm + FA_INV);
    const int tid = threadIdx.x, lane = tid & 31, w = tid >> 5;
    const int wm  = (w & 3) * 32;
    const int wnq = (w >> 2) * 16;   // QK col group (32 cols total)
    const int wnp = (w >> 2) * 32;   // PV col group (64 cols total)

    const int qt = blockIdx.x, z = blockIdx.y, b = z >> 4, h = z & 15;
    const size_t hb = (size_t)b * Sc * TD3 + h * 192;
    const __nv_bfloat16* Qgh = qkh + hb + (size_t)(qt * 128) * TD3;
    const __nv_bfloat16* Qgl = qkl + hb + (size_t)(qt * 128) * TD3;
    const __nv_bfloat16* Kgh = qkh + hb + 64;
    const __nv_bfloat16* Kgl = qkl + hb + 64;
    const __nv_bfloat16* Vgh = qkh + hb + 128;
    const __nv_bfloat16* Vgl = qkl + hb + 128;
    float* Az = attn_out + (size_t)z * Sc * Sc + (size_t)(qt * 128) * Sc;

    const int krow = tid >> 3, kc16 = tid & 7;               // 32-row chunk loads
    const uint32_t kdst = sw128((uint32_t)krow * 128 + kc16 * 16);

    // zero rowsum accumulators
    if (tid < 128) { rsacc[tid * 2] = 0.f; rsacc[tid * 2 + 1] = 0.f; }

    // prologue: group0 = {Q, K0, V0}; group1 = {K1, V1}
#pragma unroll
    for (int i = 0; i < 4; i++) {
        const int id = tid + 256 * i;
        const int row = id >> 3, c16 = id & 7;
        const uint32_t d = sw128((uint32_t)row * 128 + c16 * 16);
        const size_t so = (size_t)row * TD3 + c16 * 8;
        cp16(sb0 + FA_Q + d,         Qgh + so);
        cp16(sb0 + FA_Q + 16384 + d, Qgl + so);
    }
#pragma unroll
    for (int s = 0; s < 2; s++) {
        const size_t so = (size_t)(s * 32 + krow) * TD3 + kc16 * 8;
        const uint32_t kb = sb0 + FA_K + (uint32_t)s * 8192;
        const uint32_t vb = sb0 + FA_V + (uint32_t)s * 8192;
        cp16(kb + kdst,        Kgh + so);
        cp16(kb + 4096 + kdst, Kgl + so);
        cp16(vb + kdst,        Vgh + so);
        cp16(vb + 4096 + kdst, Vgl + so);
        cp_commit();
    }

    // ---- pass 1: S = exp(QK/8) -> smem -> PV MMA; rowsums accumulate ----
    float accv[2][4][4] = {};
#pragma unroll 1
    for (int c = 0; c < 64; c++) {
        cp_wait<1>();
        __syncthreads();
        float aq[2][2][4] = {};
        computeQK(sb0, sb0 + FA_K + (uint32_t)(c % 3) * 8192, wm, wnq, lane, aq);
        if (c + 2 < 64) {
            const int s = (c + 2) % 3;
            const size_t so = (size_t)((c + 2) * 32 + krow) * TD3 + kc16 * 8;
            const uint32_t kb = sb0 + FA_K + (uint32_t)s * 8192;
            const uint32_t vb = sb0 + FA_V + (uint32_t)s * 8192;
            cp16(kb + kdst,        Kgh + so);
            cp16(kb + 4096 + kdst, Kgl + so);
            cp16(vb + kdst,        Vgh + so);
            cp16(vb + 4096 + kdst, Vgl + so);
        }
        cp_commit();
        // exp + STS S (hi/lo) + rowsum partials
#pragma unroll
        for (int mt = 0; mt < 2; mt++) {
            float p0 = 0.f, p1 = 0.f;
            const int r  = wm + mt * 16 + (lane >> 2);
#pragma unroll
            for (int nt = 0; nt < 2; nt++) {
                const int cp2 = (wnq + nt * 8 + (lane & 3) * 2) * 2;  // byte col
                const float e0 = fexp8(aq[mt][nt][0]);
                const float e1 = fexp8(aq[mt][nt][1]);
                const float e2 = fexp8(aq[mt][nt][2]);
                const float e3 = fexp8(aq[mt][nt][3]);
                uint32_t hh, ll;
                pack_hilo(e0, e1, hh, ll);
                *reinterpret_cast<uint32_t*>(sm + FA_S +        sw64((uint32_t)r * 64 + cp2)) = hh;
                *reinterpret_cast<uint32_t*>(sm + FA_S + 8192 + sw64((uint32_t)r * 64 + cp2)) = ll;
                pack_hilo(e2, e3, hh, ll);
                *reinterpret_cast<uint32_t*>(sm + FA_S +        sw64((uint32_t)(r + 8) * 64 + cp2)) = hh;
                *reinterpret_cast<uint32_t*>(sm + FA_S + 8192 + sw64((uint32_t)(r + 8) * 64 + cp2)) = ll;
                p0 += e0 + e1;
                p1 += e2 + e3;
            }
            p0 += __shfl_xor_sync(0xFFFFFFFFu, p0, 1);
            p0 += __shfl_xor_sync(0xFFFFFFFFu, p0, 2);
            p1 += __shfl_xor_sync(0xFFFFFFFFu, p1, 1);
            p1 += __shfl_xor_sync(0xFFFFFFFFu, p1, 2);
            if ((lane & 3) == 0) {
                rsacc[r * 2 + (w >> 2)]       += p0;
                rsacc[(r + 8) * 2 + (w >> 2)] += p1;
            }
        }
        __syncthreads();
        computePV(sb0 + FA_S, sb0 + FA_V + (uint32_t)(c % 3) * 8192, wm, wnp, lane, accv);
    }

    __syncthreads();
    if (tid < 128) invp[tid] = 1.f / (rsacc[tid * 2] + rsacc[tid * 2 + 1]);
    cp_wait<0>();
    __syncthreads();

    // ---- vals epilogue: scale by inv, pack hi/lo, store ----
    {
        __nv_bfloat16* Oh = voh + (size_t)z * Sc * HDc + (size_t)(qt * 128) * HDc;
        __nv_bfloat16* Ol = vol + (size_t)z * Sc * HDc + (size_t)(qt * 128) * HDc;
        const int r0b = wm + (lane >> 2);
        const int ccb = wnp + (lane & 3) * 2;
#pragma unroll
        for (int mt = 0; mt < 2; mt++) {
            const int r0 = r0b + mt * 16;
            const float i0 = invp[r0], i1 = invp[r0 + 8];
#pragma unroll
            for (int nt = 0; nt < 4; nt++) {
                const int cc = ccb + nt * 8;
                uint32_t hh, ll;
                pack_hilo(accv[mt][nt][0] * i0, accv[mt][nt][1] * i0, hh, ll);
                *reinterpret_cast<uint32_t*>(Oh + (size_t)r0 * HDc + cc) = hh;
                *reinterpret_cast<uint32_t*>(Ol + (size_t)r0 * HDc + cc) = ll;
                pack_hilo(accv[mt][nt][2] * i1, accv[mt][nt][3] * i1, hh, ll);
                *reinterpret_cast<uint32_t*>(Oh + (size_t)(r0 + 8) * HDc + cc) = hh;
                *reinterpret_cast<uint32_t*>(Ol + (size_t)(r0 + 8) * HDc + cc) = ll;
            }
        }
    }

    // ---- pass 2: recompute QK, write normalized attention (single write) ----
#pragma unroll
    for (int s = 0; s < 2; s++) {
        const size_t so = (size_t)(s * 32 + krow) * TD3 + kc16 * 8;
        const uint32_t kb = sb0 + FA_K + (uint32_t)s * 8192;
        cp16(kb + kdst,        Kgh + so);
        cp16(kb + 4096 + kdst, Kgl + so);
        cp_commit();
    }
#pragma unroll 1
    for (int c = 0; c < 64; c++) {
        cp_wait<1>();
        __syncthreads();
        float aq[2][2][4] = {};
        computeQK(sb0, sb0 + FA_K + (uint32_t)(c % 3) * 8192, wm, wnq, lane, aq);
        if (c + 2 < 64) {
            const int s = (c + 2) % 3;
            const size_t so = (size_t)((c + 2) * 32 + krow) * TD3 + kc16 * 8;
            const uint32_t kb = sb0 + FA_K + (uint32_t)s * 8192;
            cp16(kb + kdst,        Kgh + so);
            cp16(kb + 4096 + kdst, Kgl + so);
        }
        cp_commit();
#pragma unroll
        for (int mt = 0; mt < 2; mt++) {
            const int r = wm + mt * 16 + (lane >> 2);
            const float i0 = invp[r], i1 = invp[r + 8];
#pragma unroll
            for (int nt = 0; nt < 2; nt++) {
                const int col = c * 32 + wnq + nt * 8 + (lane & 3) * 2;
                float2 v0 = {fexp8(aq[mt][nt][0]) * i0, fexp8(aq[mt][nt][1]) * i0};
                float2 v1 = {fexp8(aq[mt][nt][2]) * i1, fexp8(aq[mt][nt][3]) * i1};
                *reinterpret_cast<float2*>(Az + (size_t)r * Sc + col) = v0;
                *reinterpret_cast<float2*>(Az + (size_t)(r + 8) * Sc + col) = v1;
            }
        }
    }
}

// ---------------------------------------------------------------------------
extern "C" void kernel_launch(void* const* d_in, const int* in_sizes, int n_in,
                              void* d_out, int out_size)
{
    const float* x     = (const float*)d_in[0];
    const float* w_qkv = (const float*)d_in[1];
    const float* b_qkv = (const float*)d_in[2];
    const float* w_out = (const float*)d_in[3];
    const float* b_out = (const float*)d_in[4];
    float* out = (float*)d_out;

    const size_t BSD  = (size_t)Bc * Sc * Dc;
    const size_t BHSS = (size_t)Bc * Hc * Sc * Sc;

    float* attn_fb;
    cudaGetSymbolAddress((void**)&attn_fb, g_attn_fb);
    __nv_bfloat16 *xh, *xl, *wqh, *wql, *woh, *wol, *qkvh, *qkvl, *vh, *vl;
    cudaGetSymbolAddress((void**)&xh,   g_x_hi);   cudaGetSymbolAddress((void**)&xl,   g_x_lo);
    cudaGetSymbolAddress((void**)&wqh,  g_wq_hi);  cudaGetSymbolAddress((void**)&wql,  g_wq_lo);
    cudaGetSymbolAddress((void**)&woh,  g_wo_hi);  cudaGetSymbolAddress((void**)&wol,  g_wo_lo);
    cudaGetSymbolAddress((void**)&qkvh, g_qkv_hi); cudaGetSymbolAddress((void**)&qkvl, g_qkv_lo);
    cudaGetSymbolAddress((void**)&vh,   g_v_hi);   cudaGetSymbolAddress((void**)&vl,   g_v_lo);

    float* attn = ((size_t)out_size >= BSD + BHSS) ? (out + BSD) : attn_fb;

    cudaFuncSetAttribute(gemm_bf16<true>,  cudaFuncAttributeMaxDynamicSharedMemorySize, 98304);
    cudaFuncSetAttribute(gemm_bf16<false>, cudaFuncAttributeMaxDynamicSharedMemorySize, 98304);
    cudaFuncSetAttribute(fused_attn,       cudaFuncAttributeMaxDynamicSharedMemorySize, FA_SMEM);

    // 0) pre-split fp32 -> bf16 hi/lo
    cvt_hilo3<<<12288, 256>>>(
        (const float4*)x,     (uint2*)xh,  (uint2*)xl,
        (const float4*)w_qkv, (uint2*)wqh, (uint2*)wql,
        (const float4*)w_out, (uint2*)woh, (uint2*)wol);

    // 1) fused QKV projection -> bf16 hi/lo qkv
    gemm_bf16<true><<<dim3(TD3 / 128, Mrows / 128), 256, 98304>>>(
        xh, xl, wqh, wql, Dc, nullptr, qkvh, qkvl, TD3, b_qkv);

    // 2) fused attention: scores+softmax+PV in one kernel; attn written once
    fused_attn<<<dim3(Sc / 128, Bc * Hc), 256, FA_SMEM>>>(qkvh, qkvl, attn, vh, vl);

    // 3) output projection
    gemm_bf16<false><<<dim3(Dc / 128, Mrows / 128), 256, 98304>>>(
        vh, vl, woh, wol, Dc, out, nullptr, nullptr, Dc, b_out);
}

// round 14
// speedup vs baseline: 1.0680x; 1.0059x over previous
#include <cuda_runtime.h>
#include <cuda_bf16.h>
#include <cstdint>

// Problem constants
constexpr int Bc  = 4;
constexpr int Sc  = 2048;
constexpr int Dc  = 1024;
constexpr int Hc  = 16;
constexpr int HDc = 64;
constexpr int TD3 = 3 * Dc;          // 3072
constexpr int Mrows = Bc * Sc;       // 8192

// Scratch (device globals; no allocation in kernel_launch)
__device__ float g_attn_fb[(size_t)Bc * Hc * Sc * Sc];
__device__ __nv_bfloat16 g_x_hi[(size_t)Mrows * Dc],   g_x_lo[(size_t)Mrows * Dc];
__device__ __nv_bfloat16 g_wq_hi[(size_t)TD3 * Dc],    g_wq_lo[(size_t)TD3 * Dc];
__device__ __nv_bfloat16 g_wo_hi[(size_t)Dc * Dc],     g_wo_lo[(size_t)Dc * Dc];
__device__ __nv_bfloat16 g_qkv_hi[(size_t)Mrows * TD3], g_qkv_lo[(size_t)Mrows * TD3];
__device__ __nv_bfloat16 g_v_hi[(size_t)Mrows * Dc],   g_v_lo[(size_t)Mrows * Dc];

// ---------------------------------------------------------------------------
// helpers
// ---------------------------------------------------------------------------
__device__ __forceinline__ uint32_t smem_u32(const void* p) {
    uint32_t a;
    asm("{ .reg .u64 t; cvta.to.shared.u64 t, %1; cvt.u32.u64 %0, t; }"
        : "=r"(a) : "l"(p));
    return a;
}
__device__ __forceinline__ uint32_t sw64(uint32_t o)  { return o ^ ((o >> 3) & 0x30); }
__device__ __forceinline__ uint32_t sw128(uint32_t o) { return o ^ ((o >> 3) & 0x70); }

__device__ __forceinline__ void ldsm4(uint32_t a, uint32_t r[4]) {
    asm volatile("ldmatrix.sync.aligned.m8n8.x4.shared.b16 {%0,%1,%2,%3}, [%4];"
                 : "=r"(r[0]), "=r"(r[1]), "=r"(r[2]), "=r"(r[3]) : "r"(a));
}
__device__ __forceinline__ void ldsm4t(uint32_t a, uint32_t r[4]) {
    asm volatile("ldmatrix.sync.aligned.m8n8.x4.trans.shared.b16 {%0,%1,%2,%3}, [%4];"
                 : "=r"(r[0]), "=r"(r[1]), "=r"(r[2]), "=r"(r[3]) : "r"(a));
}
__device__ __forceinline__ void mma16816(float d[4], const uint32_t a[4], const uint32_t b[2]) {
    asm volatile(
        "mma.sync.aligned.m16n8k16.row.col.f32.bf16.bf16.f32 "
        "{%0,%1,%2,%3}, {%4,%5,%6,%7}, {%8,%9}, {%0,%1,%2,%3};"
        : "+f"(d[0]), "+f"(d[1]), "+f"(d[2]), "+f"(d[3])
        : "r"(a[0]), "r"(a[1]), "r"(a[2]), "r"(a[3]), "r"(b[0]), "r"(b[1]));
}
__device__ __forceinline__ void cp16(uint32_t dst, const void* src) {
    asm volatile("cp.async.cg.shared.global [%0], [%1], 16;" :: "r"(dst), "l"(src));
}
__device__ __forceinline__ void cp_commit() {
    asm volatile("cp.async.commit_group;" ::: "memory");
}
template <int N> __device__ __forceinline__ void cp_wait() {
    asm volatile("cp.async.wait_group %0;" :: "n"(N) : "memory");
}
__device__ __forceinline__ void split_hilo(float4 v, uint2& hw, uint2& lw) {
    __nv_bfloat162 h01 = __floats2bfloat162_rn(v.x, v.y);
    __nv_bfloat162 h23 = __floats2bfloat162_rn(v.z, v.w);
    float r0 = v.x - __low2float(h01);
    float r1 = v.y - __high2float(h01);
    float r2 = v.z - __low2float(h23);
    float r3 = v.w - __high2float(h23);
    __nv_bfloat162 l01 = __floats2bfloat162_rn(r0, r1);
    __nv_bfloat162 l23 = __floats2bfloat162_rn(r2, r3);
    hw.x = *reinterpret_cast<uint32_t*>(&h01); hw.y = *reinterpret_cast<uint32_t*>(&h23);
    lw.x = *reinterpret_cast<uint32_t*>(&l01); lw.y = *reinterpret_cast<uint32_t*>(&l23);
}
__device__ __forceinline__ void pack_hilo(float v0, float v1, uint32_t& h, uint32_t& l) {
    __nv_bfloat162 h2 = __floats2bfloat162_rn(v0, v1);
    float r0 = v0 - __low2float(h2), r1 = v1 - __high2float(h2);
    __nv_bfloat162 l2 = __floats2bfloat162_rn(r0, r1);
    h = *reinterpret_cast<uint32_t*>(&h2);
    l = *reinterpret_cast<uint32_t*>(&l2);
}
// exp(s/8) via 2^(s*0.125*log2e), degree-6 poly + exponent splice (FMA pipe).
__device__ __forceinline__ float fexp8(float s) {
    float v = s * 0.1803368801111244f;   // 0.125 * log2(e)
    float fl = floorf(v);
    float f = v - fl;
    float p = 1.5435906e-4f;
    p = fmaf(p, f, 1.3333558e-3f);
    p = fmaf(p, f, 9.6181291e-3f);
    p = fmaf(p, f, 5.5504109e-2f);
    p = fmaf(p, f, 2.4022651e-1f);
    p = fmaf(p, f, 6.9314718e-1f);
    p = fmaf(p, f, 1.0f);
    return __int_as_float(__float_as_int(p) + ((int)fl << 23));
}

// ---------------------------------------------------------------------------
// merged convert kernel: three fp32 -> (hi, lo) arrays in one launch
// ---------------------------------------------------------------------------
__global__ __launch_bounds__(256) void cvt_hilo3(
    const float4* __restrict__ in0, uint2* __restrict__ h0, uint2* __restrict__ l0,
    const float4* __restrict__ in1, uint2* __restrict__ h1, uint2* __restrict__ l1,
    const float4* __restrict__ in2, uint2* __restrict__ h2, uint2* __restrict__ l2)
{
    const int bx = blockIdx.x;
    const float4* in; uint2 *hp, *lp; int i;
    if (bx < 8192)       { in = in0; hp = h0; lp = l0; i = bx * 256 + threadIdx.x; }
    else if (bx < 11264) { in = in1; hp = h1; lp = l1; i = (bx - 8192) * 256 + threadIdx.x; }
    else                 { in = in2; hp = h2; lp = l2; i = (bx - 11264) * 256 + threadIdx.x; }
    uint2 h, l;
    split_hilo(in[i], h, l);
    hp[i] = h; lp[i] = l;
}

// ---------------------------------------------------------------------------
// GEMM compute core: one BK=32 chunk; A,B tiles 128 rows x 64B, SW64
// ---------------------------------------------------------------------------
__device__ __forceinline__ void compute64(uint32_t sb, int wm, int wn, int lane,
                                          float acc[2][8][4]) {
    const uint32_t Ah = sb, Al = sb + 8192, Bh = sb + 16384, Bl = sb + 24576;
    const int arow = ((lane >> 3) & 1) * 8 + (lane & 7);
    const int brow = ((lane >> 4) & 1) * 8 + (lane & 7);
#pragma unroll
    for (int ks = 0; ks < 2; ks++) {
        const uint32_t akb = (uint32_t)(ks * 32 + ((lane >> 4) & 1) * 16);
        const uint32_t bkb = (uint32_t)(ks * 32 + ((lane >> 3) & 1) * 16);
        uint32_t ah[2][4], al[2][4];
#pragma unroll
        for (int mt = 0; mt < 2; mt++) {
            const uint32_t off = sw64((uint32_t)(wm + mt * 16 + arow) * 64 + akb);
            ldsm4(Ah + off, ah[mt]);
            ldsm4(Al + off, al[mt]);
        }
#pragma unroll
        for (int half = 0; half < 2; half++) {
            uint32_t bh[4][2], bl[4][2];
#pragma unroll
            for (int p = 0; p < 2; p++) {
                const uint32_t off = sw64((uint32_t)(wn + (half * 2 + p) * 16 + brow) * 64 + bkb);
                uint32_t t[4];
                ldsm4(Bh + off, t);
                bh[2*p][0]=t[0]; bh[2*p][1]=t[1]; bh[2*p+1][0]=t[2]; bh[2*p+1][1]=t[3];
                ldsm4(Bl + off, t);
                bl[2*p][0]=t[0]; bl[2*p][1]=t[1]; bl[2*p+1][0]=t[2]; bl[2*p+1][1]=t[3];
            }
#pragma unroll
            for (int nt = 0; nt < 4; nt++)
#pragma unroll
                for (int mt = 0; mt < 2; mt++) {
                    mma16816(acc[mt][half*4+nt], ah[mt], bh[nt]);
                    mma16816(acc[mt][half*4+nt], ah[mt], bl[nt]);
                    mma16816(acc[mt][half*4+nt], al[mt], bh[nt]);
                }
        }
    }
}

// cp.async one 128x32 bf16 tile (8KB), SW64 rows
__device__ __forceinline__ void cp_tile(uint32_t dst_base, const __nv_bfloat16* __restrict__ src,
                                        int K, int k0, int tid)
{
#pragma unroll
    for (int i = 0; i < 2; i++) {
        const int id = tid + 256 * i;
        const int row = id >> 2, c16 = id & 3;
        cp16(dst_base + sw64((uint32_t)row * 64 + c16 * 16),
             src + (size_t)row * K + k0 + c16 * 8);
    }
}

// ---------------------------------------------------------------------------
// GEMM: C[128x128] = A @ B^T + bias; 3-stage cp.async, 2 CTAs/SM
// ---------------------------------------------------------------------------
template <bool BF16OUT>
__global__ __launch_bounds__(256, 2) void gemm_bf16(
    const __nv_bfloat16* __restrict__ Ahg, const __nv_bfloat16* __restrict__ Alg,
    const __nv_bfloat16* __restrict__ Bhg, const __nv_bfloat16* __restrict__ Blg,
    int K, float* __restrict__ C, __nv_bfloat16* __restrict__ Chi,
    __nv_bfloat16* __restrict__ Clo, int N, const float* __restrict__ bias)
{
    extern __shared__ uint8_t sm[];
    const uint32_t sb0 = smem_u32(sm);
    const int tid = threadIdx.x, lane = tid & 31, w = tid >> 5;
    const int wm = (w & 3) * 32, wn = (w >> 2) * 64;

    Ahg += (size_t)(blockIdx.y * 128) * K;
    Alg += (size_t)(blockIdx.y * 128) * K;
    Bhg += (size_t)(blockIdx.x * 128) * K;
    Blg += (size_t)(blockIdx.x * 128) * K;

    const int NC = K >> 5;
#pragma unroll 1
    for (int s = 0; s < 2; s++) {
        const uint32_t st = sb0 + (uint32_t)s * 32768;
        cp_tile(st,          Ahg, K, s * 32, tid);
        cp_tile(st + 8192,   Alg, K, s * 32, tid);
        cp_tile(st + 16384,  Bhg, K, s * 32, tid);
        cp_tile(st + 24576,  Blg, K, s * 32, tid);
        cp_commit();
    }

    float acc[2][8][4] = {};
#pragma unroll 1
    for (int c = 0; c < NC; c++) {
        cp_wait<1>();
        __syncthreads();
        if (c + 2 < NC) {
            const uint32_t st = sb0 + (uint32_t)((c + 2) % 3) * 32768;
            cp_tile(st,          Ahg, K, (c + 2) * 32, tid);
            cp_tile(st + 8192,   Alg, K, (c + 2) * 32, tid);
            cp_tile(st + 16384,  Bhg, K, (c + 2) * 32, tid);
            cp_tile(st + 24576,  Blg, K, (c + 2) * 32, tid);
        }
        cp_commit();
        compute64(sb0 + (uint32_t)(c % 3) * 32768, wm, wn, lane, acc);
    }

    const int gr = blockIdx.y * 128 + wm + (lane >> 2);
    const int gc = blockIdx.x * 128 + wn + (lane & 3) * 2;
#pragma unroll
    for (int mt = 0; mt < 2; mt++) {
        const int r0 = gr + mt * 16;
#pragma unroll
        for (int nt = 0; nt < 8; nt++) {
            const int cc = gc + nt * 8;
            const float b0 = __ldg(bias + cc), b1 = __ldg(bias + cc + 1);
            const float v00 = acc[mt][nt][0] + b0, v01 = acc[mt][nt][1] + b1;
            const float v10 = acc[mt][nt][2] + b0, v11 = acc[mt][nt][3] + b1;
            if (BF16OUT) {
                uint32_t h, l;
                pack_hilo(v00, v01, h, l);
                *reinterpret_cast<uint32_t*>(Chi + (size_t)r0 * N + cc) = h;
                *reinterpret_cast<uint32_t*>(Clo + (size_t)r0 * N + cc) = l;
                pack_hilo(v10, v11, h, l);
                *reinterpret_cast<uint32_t*>(Chi + (size_t)(r0 + 8) * N + cc) = h;
                *reinterpret_cast<uint32_t*>(Clo + (size_t)(r0 + 8) * N + cc) = l;
            } else {
                float2 u0 = {v00, v01}, u1 = {v10, v11};
                *reinterpret_cast<float2*>(C + (size_t)r0 * N + cc) = u0;
                *reinterpret_cast<float2*>(C + (size_t)(r0 + 8) * N + cc) = u1;
            }
        }
    }
}

// ---------------------------------------------------------------------------
// Fused attention.
// Pass 1 (32-row kv chunks): S = exp(QK/8) -> smem -> PV MMA; rowsums.
// Pass 2 (64-row kv chunks): recompute QK, write normalized attention once.
// smem layout (bytes):
//   Qh @0 (16K), Ql @16384 (16K)
//   pass1: K stages 3 x 8K @32768 ; V stages 3 x 8K @57344 ;
//          S hi 8K @81920, lo 8K @90112
//   pass2: K64 stages 3 x 16K @32768 (reuses K/V region)
//   rsacc[128][2] f32 @98304 ; inv[128] f32 @99328
// ---------------------------------------------------------------------------
constexpr uint32_t FA_Q   = 0;
constexpr uint32_t FA_K   = 32768;
constexpr uint32_t FA_V   = 57344;
constexpr uint32_t FA_S   = 81920;
constexpr uint32_t FA_RS  = 98304;
constexpr uint32_t FA_INV = 99328;
constexpr uint32_t FA_SMEM = 99840;

// QK chunk (32 rows): S[128 x 32] = Q[128 x 64] . K_chunk[32 x 64]^T, 3-term
__device__ __forceinline__ void computeQK(uint32_t sb0, uint32_t kb, int wm, int wnq,
                                          int lane, float aq[2][2][4]) {
    const uint32_t Qh = sb0 + FA_Q, Ql = sb0 + FA_Q + 16384;
    const uint32_t Kh = kb, Kl = kb + 4096;
    const int arow = ((lane >> 3) & 1) * 8 + (lane & 7);
    const int brow = ((lane >> 4) & 1) * 8 + (lane & 7);
#pragma unroll
    for (int ks = 0; ks < 4; ks++) {
        const uint32_t akb = (uint32_t)(ks * 32 + ((lane >> 4) & 1) * 16);
        const uint32_t bkb = (uint32_t)(ks * 32 + ((lane >> 3) & 1) * 16);
        uint32_t qh[2][4], ql_[2][4];
#pragma unroll
        for (int mt = 0; mt < 2; mt++) {
            const uint32_t off = sw128((uint32_t)(wm + mt * 16 + arow) * 128 + akb);
            ldsm4(Qh + off, qh[mt]);
            ldsm4(Ql + off, ql_[mt]);
        }
        uint32_t bh[2][2], bl[2][2], t[4];
        const uint32_t boff = sw128((uint32_t)(wnq + brow) * 128 + bkb);
        ldsm4(Kh + boff, t);
        bh[0][0]=t[0]; bh[0][1]=t[1]; bh[1][0]=t[2]; bh[1][1]=t[3];
        ldsm4(Kl + boff, t);
        bl[0][0]=t[0]; bl[0][1]=t[1]; bl[1][0]=t[2]; bl[1][1]=t[3];
#pragma unroll
        for (int nt = 0; nt < 2; nt++)
#pragma unroll
            for (int mt = 0; mt < 2; mt++) {
                mma16816(aq[mt][nt], qh[mt], bh[nt]);
                mma16816(aq[mt][nt], qh[mt], bl[nt]);
                mma16816(aq[mt][nt], ql_[mt], bh[nt]);
            }
    }
}

// QK chunk (64 rows): S[128 x 64]; warp tile 32x32; K stage = 16K (hi 8K, lo 8K)
__device__ __forceinline__ void computeQK64(uint32_t sb0, uint32_t kb, int wm, int wnq2,
                                            int lane, float aq[2][4][4]) {
    const uint32_t Qh = sb0 + FA_Q, Ql = sb0 + FA_Q + 16384;
    const uint32_t Kh = kb, Kl = kb + 8192;
    const int arow = ((lane >> 3) & 1) * 8 + (lane & 7);
    const int brow = ((lane >> 4) & 1) * 8 + (lane & 7);
#pragma unroll
    for (int ks = 0; ks < 4; ks++) {
        const uint32_t akb = (uint32_t)(ks * 32 + ((lane >> 4) & 1) * 16);
        const uint32_t bkb = (uint32_t)(ks * 32 + ((lane >> 3) & 1) * 16);
        uint32_t qh[2][4], ql_[2][4];
#pragma unroll
        for (int mt = 0; mt < 2; mt++) {
            const uint32_t off = sw128((uint32_t)(wm + mt * 16 + arow) * 128 + akb);
            ldsm4(Qh + off, qh[mt]);
            ldsm4(Ql + off, ql_[mt]);
        }
        uint32_t bh[4][2], bl[4][2];
#pragma unroll
        for (int p = 0; p < 2; p++) {
            uint32_t t[4];
            const uint32_t boff = sw128((uint32_t)(wnq2 + p * 16 + brow) * 128 + bkb);
            ldsm4(Kh + boff, t);
            bh[2*p][0]=t[0]; bh[2*p][1]=t[1]; bh[2*p+1][0]=t[2]; bh[2*p+1][1]=t[3];
            ldsm4(Kl + boff, t);
            bl[2*p][0]=t[0]; bl[2*p][1]=t[1]; bl[2*p+1][0]=t[2]; bl[2*p+1][1]=t[3];
        }
#pragma unroll
        for (int nt = 0; nt < 4; nt++)
#pragma unroll
            for (int mt = 0; mt < 2; mt++) {
                mma16816(aq[mt][nt], qh[mt], bh[nt]);
                mma16816(aq[mt][nt], qh[mt], bl[nt]);
                mma16816(aq[mt][nt], ql_[mt], bh[nt]);
            }
    }
}

// PV chunk: O += S[128 x 32] . V_chunk[32 x 64]; S SW64, V SW128 trans
__device__ __forceinline__ void computePV(uint32_t ab, uint32_t vb, int wm, int wnp,
                                          int lane, float acc[2][4][4]) {
    const uint32_t Ah = ab, Al = ab + 8192, Vh = vb, Vl = vb + 4096;
    const int arow = ((lane >> 3) & 1) * 8 + (lane & 7);
    const int krw  = ((lane >> 3) & 1) * 8 + (lane & 7);
    const int dof  = ((lane >> 4) & 1) * 8;
#pragma unroll
    for (int ks = 0; ks < 2; ks++) {
        const uint32_t akb = (uint32_t)(ks * 32 + ((lane >> 4) & 1) * 16);
        uint32_t ah[2][4], al[2][4];
#pragma unroll
        for (int mt = 0; mt < 2; mt++) {
            const uint32_t off = sw64((uint32_t)(wm + mt * 16 + arow) * 64 + akb);
            ldsm4(Ah + off, ah[mt]);
            ldsm4(Al + off, al[mt]);
        }
        uint32_t vh[4][2], vl[4][2];
#pragma unroll
        for (int p = 0; p < 2; p++) {
            const uint32_t off = sw128((uint32_t)(ks * 16 + krw) * 128 +
                                       (uint32_t)(wnp + p * 16 + dof) * 2);
            uint32_t t[4];
            ldsm4t(Vh + off, t);
            vh[2*p][0]=t[0]; vh[2*p][1]=t[1]; vh[2*p+1][0]=t[2]; vh[2*p+1][1]=t[3];
            ldsm4t(Vl + off, t);
            vl[2*p][0]=t[0]; vl[2*p][1]=t[1]; vl[2*p+1][0]=t[2]; vl[2*p+1][1]=t[3];
        }
#pragma unroll
        for (int nt = 0; nt < 4; nt++)
#pragma unroll
            for (int mt = 0; mt < 2; mt++) {
                mma16816(acc[mt][nt], ah[mt], vh[nt]);
                mma16816(acc[mt][nt], ah[mt], vl[nt]);
                mma16816(acc[mt][nt], al[mt], vh[nt]);
            }
    }
}

__global__ __launch_bounds__(256, 2) void fused_attn(
    const __nv_bfloat16* __restrict__ qkh, const __nv_bfloat16* __restrict__ qkl,
    float* __restrict__ attn_out,
    __nv_bfloat16* __restrict__ voh, __nv_bfloat16* __restrict__ vol)
{
    extern __shared__ uint8_t sm[];
    const uint32_t sb0 = smem_u32(sm);
    float* rsacc = reinterpret_cast<float*>(sm + FA_RS);
    float* invp  = reinterpret_cast<float*>(sm + FA_INV);
    const int tid = threadIdx.x, lane = tid & 31, w = tid >> 5;
    const int wm  = (w & 3) * 32;
    const int wnq = (w >> 2) * 16;   // pass1 QK col group (32 cols total)
    const int wnp = (w >> 2) * 32;   // PV col group (64 cols total)

    const int qt = blockIdx.x, z = blockIdx.y, b = z >> 4, h = z & 15;
    const size_t hb = (size_t)b * Sc * TD3 + h * 192;
    const __nv_bfloat16* Qgh = qkh + hb + (size_t)(qt * 128) * TD3;
    const __nv_bfloat16* Qgl = qkl + hb + (size_t)(qt * 128) * TD3;
    const __nv_bfloat16* Kgh = qkh + hb + 64;
    const __nv_bfloat16* Kgl = qkl + hb + 64;
    const __nv_bfloat16* Vgh = qkh + hb + 128;
    const __nv_bfloat16* Vgl = qkl + hb + 128;
    float* Az = attn_out + (size_t)z * Sc * Sc + (size_t)(qt * 128) * Sc;

    const int krow = tid >> 3, kc16 = tid & 7;               // 32-row chunk loads
    const uint32_t kdst = sw128((uint32_t)krow * 128 + kc16 * 16);

    // zero rowsum accumulators
    if (tid < 128) { rsacc[tid * 2] = 0.f; rsacc[tid * 2 + 1] = 0.f; }

    // prologue: group0 = {Q, K0, V0}; group1 = {K1, V1}
#pragma unroll
    for (int i = 0; i < 4; i++) {
        const int id = tid + 256 * i;
        const int row = id >> 3, c16 = id & 7;
        const uint32_t d = sw128((uint32_t)row * 128 + c16 * 16);
        const size_t so = (size_t)row * TD3 + c16 * 8;
        cp16(sb0 + FA_Q + d,         Qgh + so);
        cp16(sb0 + FA_Q + 16384 + d, Qgl + so);
    }
#pragma unroll
    for (int s = 0; s < 2; s++) {
        const size_t so = (size_t)(s * 32 + krow) * TD3 + kc16 * 8;
        const uint32_t kb = sb0 + FA_K + (uint32_t)s * 8192;
        const uint32_t vb = sb0 + FA_V + (uint32_t)s * 8192;
        cp16(kb + kdst,        Kgh + so);
        cp16(kb + 4096 + kdst, Kgl + so);
        cp16(vb + kdst,        Vgh + so);
        cp16(vb + 4096 + kdst, Vgl + so);
        cp_commit();
    }

    // ---- pass 1: S = exp(QK/8) -> smem -> PV MMA; rowsums accumulate ----
    float accv[2][4][4] = {};
#pragma unroll 1
    for (int c = 0; c < 64; c++) {
        cp_wait<1>();
        __syncthreads();
        float aq[2][2][4] = {};
        computeQK(sb0, sb0 + FA_K + (uint32_t)(c % 3) * 8192, wm, wnq, lane, aq);
        if (c + 2 < 64) {
            const int s = (c + 2) % 3;
            const size_t so = (size_t)((c + 2) * 32 + krow) * TD3 + kc16 * 8;
            const uint32_t kb = sb0 + FA_K + (uint32_t)s * 8192;
            const uint32_t vb = sb0 + FA_V + (uint32_t)s * 8192;
            cp16(kb + kdst,        Kgh + so);
            cp16(kb + 4096 + kdst, Kgl + so);
            cp16(vb + kdst,        Vgh + so);
            cp16(vb + 4096 + kdst, Vgl + so);
        }
        cp_commit();
        // exp + STS S (hi/lo) + rowsum partials
#pragma unroll
        for (int mt = 0; mt < 2; mt++) {
            float p0 = 0.f, p1 = 0.f;
            const int r  = wm + mt * 16 + (lane >> 2);
#pragma unroll
            for (int nt = 0; nt < 2; nt++) {
                const int cp2 = (wnq + nt * 8 + (lane & 3) * 2) * 2;  // byte col
                const float e0 = fexp8(aq[mt][nt][0]);
                const float e1 = fexp8(aq[mt][nt][1]);
                const float e2 = fexp8(aq[mt][nt][2]);
                const float e3 = fexp8(aq[mt][nt][3]);
                uint32_t hh, ll;
                pack_hilo(e0, e1, hh, ll);
                *reinterpret_cast<uint32_t*>(sm + FA_S +        sw64((uint32_t)r * 64 + cp2)) = hh;
                *reinterpret_cast<uint32_t*>(sm + FA_S + 8192 + sw64((uint32_t)r * 64 + cp2)) = ll;
                pack_hilo(e2, e3, hh, ll);
                *reinterpret_cast<uint32_t*>(sm + FA_S +        sw64((uint32_t)(r + 8) * 64 + cp2)) = hh;
                *reinterpret_cast<uint32_t*>(sm + FA_S + 8192 + sw64((uint32_t)(r + 8) * 64 + cp2)) = ll;
                p0 += e0 + e1;
                p1 += e2 + e3;
            }
            p0 += __shfl_xor_sync(0xFFFFFFFFu, p0, 1);
            p0 += __shfl_xor_sync(0xFFFFFFFFu, p0, 2);
            p1 += __shfl_xor_sync(0xFFFFFFFFu, p1, 1);
            p1 += __shfl_xor_sync(0xFFFFFFFFu, p1, 2);
            if ((lane & 3) == 0) {
                rsacc[r * 2 + (w >> 2)]       += p0;
                rsacc[(r + 8) * 2 + (w >> 2)] += p1;
            }
        }
        __syncthreads();
        computePV(sb0 + FA_S, sb0 + FA_V + (uint32_t)(c % 3) * 8192, wm, wnp, lane, accv);
    }

    __syncthreads();
    if (tid < 128) invp[tid] = 1.f / (rsacc[tid * 2] + rsacc[tid * 2 + 1]);
    cp_wait<0>();
    __syncthreads();

    // ---- vals epilogue: scale by inv, pack hi/lo, store ----
    {
        __nv_bfloat16* Oh = voh + (size_t)z * Sc * HDc + (size_t)(qt * 128) * HDc;
        __nv_bfloat16* Ol = vol + (size_t)z * Sc * HDc + (size_t)(qt * 128) * HDc;
        const int r0b = wm + (lane >> 2);
        const int ccb = wnp + (lane & 3) * 2;
#pragma unroll
        for (int mt = 0; mt < 2; mt++) {
            const int r0 = r0b + mt * 16;
            const float i0 = invp[r0], i1 = invp[r0 + 8];
#pragma unroll
            for (int nt = 0; nt < 4; nt++) {
                const int cc = ccb + nt * 8;
                uint32_t hh, ll;
                pack_hilo(accv[mt][nt][0] * i0, accv[mt][nt][1] * i0, hh, ll);
                *reinterpret_cast<uint32_t*>(Oh + (size_t)r0 * HDc + cc) = hh;
                *reinterpret_cast<uint32_t*>(Ol + (size_t)r0 * HDc + cc) = ll;
                pack_hilo(accv[mt][nt][2] * i1, accv[mt][nt][3] * i1, hh, ll);
                *reinterpret_cast<uint32_t*>(Oh + (size_t)(r0 + 8) * HDc + cc) = hh;
                *reinterpret_cast<uint32_t*>(Ol + (size_t)(r0 + 8) * HDc + cc) = ll;
            }
        }
    }

    // ---- pass 2: recompute QK in 64-row chunks, write normalized attn ----
    // K64 stage = 16K { hi 8K, lo 8K }, 3 stages @FA_K
    const int k2row = tid >> 2, k2c16 = tid & 3;   // 64 rows, 2 cp16/plane/thread... 
    const int wnq2 = (w >> 2) * 32;
#pragma unroll
    for (int s = 0; s < 2; s++) {
        const uint32_t kb = sb0 + FA_K + (uint32_t)s * 16384;
#pragma unroll
        for (int i = 0; i < 2; i++) {
            const int id = tid + 256 * i;
            const int row = id >> 3, c16 = id & 7;
            const uint32_t d = sw128((uint32_t)row * 128 + c16 * 16);
            const size_t so = (size_t)(s * 64 + row) * TD3 + c16 * 8;
            cp16(kb + d,        Kgh + so);
            cp16(kb + 8192 + d, Kgl + so);
        }
        cp_commit();
    }
#pragma unroll 1
    for (int c = 0; c < 32; c++) {
        cp_wait<1>();
        __syncthreads();
        float aq[2][4][4] = {};
        computeQK64(sb0, sb0 + FA_K + (uint32_t)(c % 3) * 16384, wm, wnq2, lane, aq);
        if (c + 2 < 32) {
            const uint32_t kb = sb0 + FA_K + (uint32_t)((c + 2) % 3) * 16384;
#pragma unroll
            for (int i = 0; i < 2; i++) {
                const int id = tid + 256 * i;
                const int row = id >> 3, c16 = id & 7;
                const uint32_t d = sw128((uint32_t)row * 128 + c16 * 16);
                const size_t so = (size_t)((c + 2) * 64 + row) * TD3 + c16 * 8;
                cp16(kb + d,        Kgh + so);
                cp16(kb + 8192 + d, Kgl + so);
            }
        }
        cp_commit();
#pragma unroll
        for (int mt = 0; mt < 2; mt++) {
            const int r = wm + mt * 16 + (lane >> 2);
            const float i0 = invp[r], i1 = invp[r + 8];
#pragma unroll
            for (int nt = 0; nt < 4; nt++) {
                const int col = c * 64 + wnq2 + nt * 8 + (lane & 3) * 2;
                float2 v0 = {fexp8(aq[mt][nt][0]) * i0, fexp8(aq[mt][nt][1]) * i0};
                float2 v1 = {fexp8(aq[mt][nt][2]) * i1, fexp8(aq[mt][nt][3]) * i1};
                *reinterpret_cast<float2*>(Az + (size_t)r * Sc + col) = v0;
                *reinterpret_cast<float2*>(Az + (size_t)(r + 8) * Sc + col) = v1;
            }
        }
    }
    (void)k2row; (void)k2c16;
}

// ---------------------------------------------------------------------------
extern "C" void kernel_launch(void* const* d_in, const int* in_sizes, int n_in,
                              void* d_out, int out_size)
{
    const float* x     = (const float*)d_in[0];
    const float* w_qkv = (const float*)d_in[1];
    const float* b_qkv = (const float*)d_in[2];
    const float* w_out = (const float*)d_in[3];
    const float* b_out = (const float*)d_in[4];
    float* out = (float*)d_out;

    const size_t BSD  = (size_t)Bc * Sc * Dc;
    const size_t BHSS = (size_t)Bc * Hc * Sc * Sc;

    float* attn_fb;
    cudaGetSymbolAddress((void**)&attn_fb, g_attn_fb);
    __nv_bfloat16 *xh, *xl, *wqh, *wql, *woh, *wol, *qkvh, *qkvl, *vh, *vl;
    cudaGetSymbolAddress((void**)&xh,   g_x_hi);   cudaGetSymbolAddress((void**)&xl,   g_x_lo);
    cudaGetSymbolAddress((void**)&wqh,  g_wq_hi);  cudaGetSymbolAddress((void**)&wql,  g_wq_lo);
    cudaGetSymbolAddress((void**)&woh,  g_wo_hi);  cudaGetSymbolAddress((void**)&wol,  g_wo_lo);
    cudaGetSymbolAddress((void**)&qkvh, g_qkv_hi); cudaGetSymbolAddress((void**)&qkvl, g_qkv_lo);
    cudaGetSymbolAddress((void**)&vh,   g_v_hi);   cudaGetSymbolAddress((void**)&vl,   g_v_lo);

    float* attn = ((size_t)out_size >= BSD + BHSS) ? (out + BSD) : attn_fb;

    cudaFuncSetAttribute(gemm_bf16<true>,  cudaFuncAttributeMaxDynamicSharedMemorySize, 98304);
    cudaFuncSetAttribute(gemm_bf16<false>, cudaFuncAttributeMaxDynamicSharedMemorySize, 98304);
    cudaFuncSetAttribute(fused_attn,       cudaFuncAttributeMaxDynamicSharedMemorySize, FA_SMEM);

    // 0) pre-split fp32 -> bf16 hi/lo
    cvt_hilo3<<<12288, 256>>>(
        (const float4*)x,     (uint2*)xh,  (uint2*)xl,
        (const float4*)w_qkv, (uint2*)wqh, (uint2*)wql,
        (const float4*)w_out, (uint2*)woh, (uint2*)wol);

    // 1) fused QKV projection -> bf16 hi/lo qkv
    gemm_bf16<true><<<dim3(TD3 / 128, Mrows / 128), 256, 98304>>>(
        xh, xl, wqh, wql, Dc, nullptr, qkvh, qkvl, TD3, b_qkv);

    // 2) fused attention: scores+softmax+PV in one kernel; attn written once
    fused_attn<<<dim3(Sc / 128, Bc * Hc), 256, FA_SMEM>>>(qkvh, qkvl, attn, vh, vl);

    // 3) output projection
    gemm_bf16<false><<<dim3(Dc / 128, Mrows / 128), 256, 98304>>>(
        vh, vl, woh, wol, Dc, out, nullptr, nullptr, Dc, b_out);
}

// round 15
// speedup vs baseline: 1.1132x; 1.0423x over previous
#include <cuda_runtime.h>
#include <cuda_bf16.h>
#include <cstdint>

// Problem constants
constexpr int Bc  = 4;
constexpr int Sc  = 2048;
constexpr int Dc  = 1024;
constexpr int Hc  = 16;
constexpr int HDc = 64;
constexpr int TD3 = 3 * Dc;          // 3072
constexpr int Mrows = Bc * Sc;       // 8192

// Scratch (device globals; no allocation in kernel_launch)
__device__ float g_attn_fb[(size_t)Bc * Hc * Sc * Sc];
__device__ __nv_bfloat16 g_x_hi[(size_t)Mrows * Dc],   g_x_lo[(size_t)Mrows * Dc];
__device__ __nv_bfloat16 g_wq_hi[(size_t)TD3 * Dc],    g_wq_lo[(size_t)TD3 * Dc];
__device__ __nv_bfloat16 g_wo_hi[(size_t)Dc * Dc],     g_wo_lo[(size_t)Dc * Dc];
__device__ __nv_bfloat16 g_qkv_hi[(size_t)Mrows * TD3], g_qkv_lo[(size_t)Mrows * TD3];
__device__ __nv_bfloat16 g_v_hi[(size_t)Mrows * Dc],   g_v_lo[(size_t)Mrows * Dc];

// ---------------------------------------------------------------------------
// helpers
// ---------------------------------------------------------------------------
__device__ __forceinline__ uint32_t smem_u32(const void* p) {
    uint32_t a;
    asm("{ .reg .u64 t; cvta.to.shared.u64 t, %1; cvt.u32.u64 %0, t; }"
        : "=r"(a) : "l"(p));
    return a;
}
__device__ __forceinline__ uint32_t sw64(uint32_t o)  { return o ^ ((o >> 3) & 0x30); }
__device__ __forceinline__ uint32_t sw128(uint32_t o) { return o ^ ((o >> 3) & 0x70); }

__device__ __forceinline__ void ldsm4(uint32_t a, uint32_t r[4]) {
    asm volatile("ldmatrix.sync.aligned.m8n8.x4.shared.b16 {%0,%1,%2,%3}, [%4];"
                 : "=r"(r[0]), "=r"(r[1]), "=r"(r[2]), "=r"(r[3]) : "r"(a));
}
__device__ __forceinline__ void ldsm4t(uint32_t a, uint32_t r[4]) {
    asm volatile("ldmatrix.sync.aligned.m8n8.x4.trans.shared.b16 {%0,%1,%2,%3}, [%4];"
                 : "=r"(r[0]), "=r"(r[1]), "=r"(r[2]), "=r"(r[3]) : "r"(a));
}
__device__ __forceinline__ void mma16816(float d[4], const uint32_t a[4], const uint32_t b[2]) {
    asm volatile(
        "mma.sync.aligned.m16n8k16.row.col.f32.bf16.bf16.f32 "
        "{%0,%1,%2,%3}, {%4,%5,%6,%7}, {%8,%9}, {%0,%1,%2,%3};"
        : "+f"(d[0]), "+f"(d[1]), "+f"(d[2]), "+f"(d[3])
        : "r"(a[0]), "r"(a[1]), "r"(a[2]), "r"(a[3]), "r"(b[0]), "r"(b[1]));
}
__device__ __forceinline__ void cp16(uint32_t dst, const void* src) {
    asm volatile("cp.async.cg.shared.global [%0], [%1], 16;" :: "r"(dst), "l"(src));
}
__device__ __forceinline__ void cp_commit() {
    asm volatile("cp.async.commit_group;" ::: "memory");
}
template <int N> __device__ __forceinline__ void cp_wait() {
    asm volatile("cp.async.wait_group %0;" :: "n"(N) : "memory");
}
__device__ __forceinline__ void split_hilo(float4 v, uint2& hw, uint2& lw) {
    __nv_bfloat162 h01 = __floats2bfloat162_rn(v.x, v.y);
    __nv_bfloat162 h23 = __floats2bfloat162_rn(v.z, v.w);
    float r0 = v.x - __low2float(h01);
    float r1 = v.y - __high2float(h01);
    float r2 = v.z - __low2float(h23);
    float r3 = v.w - __high2float(h23);
    __nv_bfloat162 l01 = __floats2bfloat162_rn(r0, r1);
    __nv_bfloat162 l23 = __floats2bfloat162_rn(r2, r3);
    hw.x = *reinterpret_cast<uint32_t*>(&h01); hw.y = *reinterpret_cast<uint32_t*>(&h23);
    lw.x = *reinterpret_cast<uint32_t*>(&l01); lw.y = *reinterpret_cast<uint32_t*>(&l23);
}
__device__ __forceinline__ void pack_hilo(float v0, float v1, uint32_t& h, uint32_t& l) {
    __nv_bfloat162 h2 = __floats2bfloat162_rn(v0, v1);
    float r0 = v0 - __low2float(h2), r1 = v1 - __high2float(h2);
    __nv_bfloat162 l2 = __floats2bfloat162_rn(r0, r1);
    h = *reinterpret_cast<uint32_t*>(&h2);
    l = *reinterpret_cast<uint32_t*>(&l2);
}
// exp(s/8) via 2^(s*0.125*log2e), degree-6 poly + exponent splice (FMA pipe).
__device__ __forceinline__ float fexp8(float s) {
    float v = s * 0.1803368801111244f;   // 0.125 * log2(e)
    float fl = floorf(v);
    float f = v - fl;
    float p = 1.5435906e-4f;
    p = fmaf(p, f, 1.3333558e-3f);
    p = fmaf(p, f, 9.6181291e-3f);
    p = fmaf(p, f, 5.5504109e-2f);
    p = fmaf(p, f, 2.4022651e-1f);
    p = fmaf(p, f, 6.9314718e-1f);
    p = fmaf(p, f, 1.0f);
    return __int_as_float(__float_as_int(p) + ((int)fl << 23));
}

// ---------------------------------------------------------------------------
// merged convert kernel: three fp32 -> (hi, lo) arrays in one launch
// ---------------------------------------------------------------------------
__global__ __launch_bounds__(256) void cvt_hilo3(
    const float4* __restrict__ in0, uint2* __restrict__ h0, uint2* __restrict__ l0,
    const float4* __restrict__ in1, uint2* __restrict__ h1, uint2* __restrict__ l1,
    const float4* __restrict__ in2, uint2* __restrict__ h2, uint2* __restrict__ l2)
{
    const int bx = blockIdx.x;
    const float4* in; uint2 *hp, *lp; int i;
    if (bx < 8192)       { in = in0; hp = h0; lp = l0; i = bx * 256 + threadIdx.x; }
    else if (bx < 11264) { in = in1; hp = h1; lp = l1; i = (bx - 8192) * 256 + threadIdx.x; }
    else                 { in = in2; hp = h2; lp = l2; i = (bx - 11264) * 256 + threadIdx.x; }
    uint2 h, l;
    split_hilo(in[i], h, l);
    hp[i] = h; lp[i] = l;
}

// ---------------------------------------------------------------------------
// GEMM compute core: one BK=32 chunk; A,B tiles 128 rows x 64B, SW64
// ---------------------------------------------------------------------------
__device__ __forceinline__ void compute64(uint32_t sb, int wm, int wn, int lane,
                                          float acc[2][8][4]) {
    const uint32_t Ah = sb, Al = sb + 8192, Bh = sb + 16384, Bl = sb + 24576;
    const int arow = ((lane >> 3) & 1) * 8 + (lane & 7);
    const int brow = ((lane >> 4) & 1) * 8 + (lane & 7);
#pragma unroll
    for (int ks = 0; ks < 2; ks++) {
        const uint32_t akb = (uint32_t)(ks * 32 + ((lane >> 4) & 1) * 16);
        const uint32_t bkb = (uint32_t)(ks * 32 + ((lane >> 3) & 1) * 16);
        uint32_t ah[2][4], al[2][4];
#pragma unroll
        for (int mt = 0; mt < 2; mt++) {
            const uint32_t off = sw64((uint32_t)(wm + mt * 16 + arow) * 64 + akb);
            ldsm4(Ah + off, ah[mt]);
            ldsm4(Al + off, al[mt]);
        }
#pragma unroll
        for (int half = 0; half < 2; half++) {
            uint32_t bh[4][2], bl[4][2];
#pragma unroll
            for (int p = 0; p < 2; p++) {
                const uint32_t off = sw64((uint32_t)(wn + (half * 2 + p) * 16 + brow) * 64 + bkb);
                uint32_t t[4];
                ldsm4(Bh + off, t);
                bh[2*p][0]=t[0]; bh[2*p][1]=t[1]; bh[2*p+1][0]=t[2]; bh[2*p+1][1]=t[3];
                ldsm4(Bl + off, t);
                bl[2*p][0]=t[0]; bl[2*p][1]=t[1]; bl[2*p+1][0]=t[2]; bl[2*p+1][1]=t[3];
            }
#pragma unroll
            for (int nt = 0; nt < 4; nt++)
#pragma unroll
                for (int mt = 0; mt < 2; mt++) {
                    mma16816(acc[mt][half*4+nt], ah[mt], bh[nt]);
                    mma16816(acc[mt][half*4+nt], ah[mt], bl[nt]);
                    mma16816(acc[mt][half*4+nt], al[mt], bh[nt]);
                }
        }
    }
}

// cp.async one 128x32 bf16 tile (8KB), SW64 rows
__device__ __forceinline__ void cp_tile(uint32_t dst_base, const __nv_bfloat16* __restrict__ src,
                                        int K, int k0, int tid)
{
#pragma unroll
    for (int i = 0; i < 2; i++) {
        const int id = tid + 256 * i;
        const int row = id >> 2, c16 = id & 3;
        cp16(dst_base + sw64((uint32_t)row * 64 + c16 * 16),
             src + (size_t)row * K + k0 + c16 * 8);
    }
}

// ---------------------------------------------------------------------------
// GEMM: C[128x128] = A @ B^T + bias; 3-stage cp.async, 2 CTAs/SM
// ---------------------------------------------------------------------------
template <bool BF16OUT>
__global__ __launch_bounds__(256, 2) void gemm_bf16(
    const __nv_bfloat16* __restrict__ Ahg, const __nv_bfloat16* __restrict__ Alg,
    const __nv_bfloat16* __restrict__ Bhg, const __nv_bfloat16* __restrict__ Blg,
    int K, float* __restrict__ C, __nv_bfloat16* __restrict__ Chi,
    __nv_bfloat16* __restrict__ Clo, int N, const float* __restrict__ bias)
{
    extern __shared__ uint8_t sm[];
    const uint32_t sb0 = smem_u32(sm);
    const int tid = threadIdx.x, lane = tid & 31, w = tid >> 5;
    const int wm = (w & 3) * 32, wn = (w >> 2) * 64;

    Ahg += (size_t)(blockIdx.y * 128) * K;
    Alg += (size_t)(blockIdx.y * 128) * K;
    Bhg += (size_t)(blockIdx.x * 128) * K;
    Blg += (size_t)(blockIdx.x * 128) * K;

    const int NC = K >> 5;
#pragma unroll 1
    for (int s = 0; s < 2; s++) {
        const uint32_t st = sb0 + (uint32_t)s * 32768;
        cp_tile(st,          Ahg, K, s * 32, tid);
        cp_tile(st + 8192,   Alg, K, s * 32, tid);
        cp_tile(st + 16384,  Bhg, K, s * 32, tid);
        cp_tile(st + 24576,  Blg, K, s * 32, tid);
        cp_commit();
    }

    float acc[2][8][4] = {};
#pragma unroll 1
    for (int c = 0; c < NC; c++) {
        cp_wait<1>();
        __syncthreads();
        if (c + 2 < NC) {
            const uint32_t st = sb0 + (uint32_t)((c + 2) % 3) * 32768;
            cp_tile(st,          Ahg, K, (c + 2) * 32, tid);
            cp_tile(st + 8192,   Alg, K, (c + 2) * 32, tid);
            cp_tile(st + 16384,  Bhg, K, (c + 2) * 32, tid);
            cp_tile(st + 24576,  Blg, K, (c + 2) * 32, tid);
        }
        cp_commit();
        compute64(sb0 + (uint32_t)(c % 3) * 32768, wm, wn, lane, acc);
    }

    const int gr = blockIdx.y * 128 + wm + (lane >> 2);
    const int gc = blockIdx.x * 128 + wn + (lane & 3) * 2;
#pragma unroll
    for (int mt = 0; mt < 2; mt++) {
        const int r0 = gr + mt * 16;
#pragma unroll
        for (int nt = 0; nt < 8; nt++) {
            const int cc = gc + nt * 8;
            const float b0 = __ldg(bias + cc), b1 = __ldg(bias + cc + 1);
            const float v00 = acc[mt][nt][0] + b0, v01 = acc[mt][nt][1] + b1;
            const float v10 = acc[mt][nt][2] + b0, v11 = acc[mt][nt][3] + b1;
            if (BF16OUT) {
                uint32_t h, l;
                pack_hilo(v00, v01, h, l);
                *reinterpret_cast<uint32_t*>(Chi + (size_t)r0 * N + cc) = h;
                *reinterpret_cast<uint32_t*>(Clo + (size_t)r0 * N + cc) = l;
                pack_hilo(v10, v11, h, l);
                *reinterpret_cast<uint32_t*>(Chi + (size_t)(r0 + 8) * N + cc) = h;
                *reinterpret_cast<uint32_t*>(Clo + (size_t)(r0 + 8) * N + cc) = l;
            } else {
                float2 u0 = {v00, v01}, u1 = {v10, v11};
                *reinterpret_cast<float2*>(C + (size_t)r0 * N + cc) = u0;
                *reinterpret_cast<float2*>(C + (size_t)(r0 + 8) * N + cc) = u1;
            }
        }
    }
}

// ---------------------------------------------------------------------------
// Fused attention.
// Pass 1 (row-split warps, register S): each warp owns 16 q-rows x all 32 kv.
//   QK C-frags -> exp in regs -> pack directly into PV A-frags (hi/lo).
//   One __syncthreads per chunk; no S smem tile; rowsums in registers.
// Pass 2 (64-row kv chunks): recompute QK, write normalized attention once.
// smem layout (bytes):
//   Qh @0 (16K), Ql @16384 (16K)
//   pass1: K stages 3 x 8K @32768 ; V stages 3 x 8K @57344
//   pass2: K64 stages 3 x 16K @32768 (reuses K/V region, ends @81920)
//   rsacc[128] f32 @81920 ; inv[128] f32 @82432
// ---------------------------------------------------------------------------
constexpr uint32_t FA_Q   = 0;
constexpr uint32_t FA_K   = 32768;
constexpr uint32_t FA_V   = 57344;
constexpr uint32_t FA_RS  = 81920;
constexpr uint32_t FA_INV = 82432;
constexpr uint32_t FA_SMEM = 82944;

// QK chunk (warp tile 16 rows x 32 kv): 4 n8 C-frags, 3-term bf16
__device__ __forceinline__ void computeQK16(uint32_t sb0, uint32_t kb, int wm,
                                            int lane, float aq[4][4]) {
    const uint32_t Qh = sb0 + FA_Q, Ql = sb0 + FA_Q + 16384;
    const uint32_t Kh = kb, Kl = kb + 4096;
    const int arow = ((lane >> 3) & 1) * 8 + (lane & 7);
    const int brow = ((lane >> 4) & 1) * 8 + (lane & 7);
#pragma unroll
    for (int ks = 0; ks < 4; ks++) {
        const uint32_t akb = (uint32_t)(ks * 32 + ((lane >> 4) & 1) * 16);
        const uint32_t bkb = (uint32_t)(ks * 32 + ((lane >> 3) & 1) * 16);
        uint32_t qh[4], ql_[4];
        const uint32_t aoff = sw128((uint32_t)(wm + arow) * 128 + akb);
        ldsm4(Qh + aoff, qh);
        ldsm4(Ql + aoff, ql_);
        uint32_t bh[4][2], bl[4][2];
#pragma unroll
        for (int p = 0; p < 2; p++) {
            uint32_t t[4];
            const uint32_t boff = sw128((uint32_t)(p * 16 + brow) * 128 + bkb);
            ldsm4(Kh + boff, t);
            bh[2*p][0]=t[0]; bh[2*p][1]=t[1]; bh[2*p+1][0]=t[2]; bh[2*p+1][1]=t[3];
            ldsm4(Kl + boff, t);
            bl[2*p][0]=t[0]; bl[2*p][1]=t[1]; bl[2*p+1][0]=t[2]; bl[2*p+1][1]=t[3];
        }
#pragma unroll
        for (int nt = 0; nt < 4; nt++) {
            mma16816(aq[nt], qh, bh[nt]);
            mma16816(aq[nt], qh, bl[nt]);
            mma16816(aq[nt], ql_, bh[nt]);
        }
    }
}

// QK chunk (64 rows): S[128 x 64]; warp tile 32x32; K stage = 16K (hi 8K, lo 8K)
__device__ __forceinline__ void computeQK64(uint32_t sb0, uint32_t kb, int wm2, int wnq2,
                                            int lane, float aq[2][4][4]) {
    const uint32_t Qh = sb0 + FA_Q, Ql = sb0 + FA_Q + 16384;
    const uint32_t Kh = kb, Kl = kb + 8192;
    const int arow = ((lane >> 3) & 1) * 8 + (lane & 7);
    const int brow = ((lane >> 4) & 1) * 8 + (lane & 7);
#pragma unroll
    for (int ks = 0; ks < 4; ks++) {
        const uint32_t akb = (uint32_t)(ks * 32 + ((lane >> 4) & 1) * 16);
        const uint32_t bkb = (uint32_t)(ks * 32 + ((lane >> 3) & 1) * 16);
        uint32_t qh[2][4], ql_[2][4];
#pragma unroll
        for (int mt = 0; mt < 2; mt++) {
            const uint32_t off = sw128((uint32_t)(wm2 + mt * 16 + arow) * 128 + akb);
            ldsm4(Qh + off, qh[mt]);
            ldsm4(Ql + off, ql_[mt]);
        }
        uint32_t bh[4][2], bl[4][2];
#pragma unroll
        for (int p = 0; p < 2; p++) {
            uint32_t t[4];
            const uint32_t boff = sw128((uint32_t)(wnq2 + p * 16 + brow) * 128 + bkb);
            ldsm4(Kh + boff, t);
            bh[2*p][0]=t[0]; bh[2*p][1]=t[1]; bh[2*p+1][0]=t[2]; bh[2*p+1][1]=t[3];
            ldsm4(Kl + boff, t);
            bl[2*p][0]=t[0]; bl[2*p][1]=t[1]; bl[2*p+1][0]=t[2]; bl[2*p+1][1]=t[3];
        }
#pragma unroll
        for (int nt = 0; nt < 4; nt++)
#pragma unroll
            for (int mt = 0; mt < 2; mt++) {
                mma16816(aq[mt][nt], qh[mt], bh[nt]);
                mma16816(aq[mt][nt], qh[mt], bl[nt]);
                mma16816(aq[mt][nt], ql_[mt], bh[nt]);
            }
    }
}

__global__ __launch_bounds__(256, 2) void fused_attn(
    const __nv_bfloat16* __restrict__ qkh, const __nv_bfloat16* __restrict__ qkl,
    float* __restrict__ attn_out,
    __nv_bfloat16* __restrict__ voh, __nv_bfloat16* __restrict__ vol)
{
    extern __shared__ uint8_t sm[];
    const uint32_t sb0 = smem_u32(sm);
    float* rsacc = reinterpret_cast<float*>(sm + FA_RS);
    float* invp  = reinterpret_cast<float*>(sm + FA_INV);
    const int tid = threadIdx.x, lane = tid & 31, w = tid >> 5;
    const int wm = w * 16;           // pass1: each warp owns 16 q-rows

    const int qt = blockIdx.x, z = blockIdx.y, b = z >> 4, h = z & 15;
    const size_t hb = (size_t)b * Sc * TD3 + h * 192;
    const __nv_bfloat16* Qgh = qkh + hb + (size_t)(qt * 128) * TD3;
    const __nv_bfloat16* Qgl = qkl + hb + (size_t)(qt * 128) * TD3;
    const __nv_bfloat16* Kgh = qkh + hb + 64;
    const __nv_bfloat16* Kgl = qkl + hb + 64;
    const __nv_bfloat16* Vgh = qkh + hb + 128;
    const __nv_bfloat16* Vgl = qkl + hb + 128;
    float* Az = attn_out + (size_t)z * Sc * Sc + (size_t)(qt * 128) * Sc;

    const int krow = tid >> 3, kc16 = tid & 7;               // 32-row chunk loads
    const uint32_t kdst = sw128((uint32_t)krow * 128 + kc16 * 16);

    // prologue: Q + chunks 0,1 of K,V (one commit group per chunk incl. Q in g0)
#pragma unroll
    for (int i = 0; i < 4; i++) {
        const int id = tid + 256 * i;
        const int row = id >> 3, c16 = id & 7;
        const uint32_t d = sw128((uint32_t)row * 128 + c16 * 16);
        const size_t so = (size_t)row * TD3 + c16 * 8;
        cp16(sb0 + FA_Q + d,         Qgh + so);
        cp16(sb0 + FA_Q + 16384 + d, Qgl + so);
    }
#pragma unroll
    for (int s = 0; s < 2; s++) {
        const size_t so = (size_t)(s * 32 + krow) * TD3 + kc16 * 8;
        const uint32_t kb = sb0 + FA_K + (uint32_t)s * 8192;
        const uint32_t vb = sb0 + FA_V + (uint32_t)s * 8192;
        cp16(kb + kdst,        Kgh + so);
        cp16(kb + 4096 + kdst, Kgl + so);
        cp16(vb + kdst,        Vgh + so);
        cp16(vb + 4096 + kdst, Vgl + so);
        cp_commit();
    }

    // ---- pass 1: QK C-frags -> exp -> A-frags -> PV; one sync per chunk ----
    float accv[8][4] = {};
    float rs0 = 0.f, rs1 = 0.f;
    const int krw = ((lane >> 3) & 1) * 8 + (lane & 7);   // V ldsm4t row pattern
    const int dof = ((lane >> 4) & 1) * 8;
#pragma unroll 1
    for (int c = 0; c < 64; c++) {
        cp_wait<1>();
        __syncthreads();
        float aq[4][4] = {};
        computeQK16(sb0, sb0 + FA_K + (uint32_t)(c % 3) * 8192, wm, lane, aq);
        if (c + 2 < 64) {
            const int s = (c + 2) % 3;
            const size_t so = (size_t)((c + 2) * 32 + krow) * TD3 + kc16 * 8;
            const uint32_t kb = sb0 + FA_K + (uint32_t)s * 8192;
            const uint32_t vb = sb0 + FA_V + (uint32_t)s * 8192;
            cp16(kb + kdst,        Kgh + so);
            cp16(kb + 4096 + kdst, Kgl + so);
            cp16(vb + kdst,        Vgh + so);
            cp16(vb + 4096 + kdst, Vgl + so);
        }
        cp_commit();
        // exp in regs + pack C-frag pairs into PV A-frags (hi/lo), rowsums in regs
        uint32_t sah[2][4], sal[2][4];
#pragma unroll
        for (int nt = 0; nt < 4; nt++) {
            const float e0 = fexp8(aq[nt][0]);
            const float e1 = fexp8(aq[nt][1]);
            const float e2 = fexp8(aq[nt][2]);
            const float e3 = fexp8(aq[nt][3]);
            rs0 += e0 + e1;
            rs1 += e2 + e3;
            const int f = nt >> 1, half = nt & 1;  // frag f, a-reg pair (0,1) or (2,3)
            pack_hilo(e0, e1, sah[f][half * 2],     sal[f][half * 2]);
            pack_hilo(e2, e3, sah[f][half * 2 + 1], sal[f][half * 2 + 1]);
        }
        // PV: O[16x64] += Sfrag(16x32) @ V(32x64)
        const uint32_t vb = sb0 + FA_V + (uint32_t)(c % 3) * 8192;
#pragma unroll
        for (int ks = 0; ks < 2; ks++) {
            uint32_t vh[8][2], vl[8][2];
#pragma unroll
            for (int p = 0; p < 4; p++) {
                const uint32_t off = sw128((uint32_t)(ks * 16 + krw) * 128 +
                                           (uint32_t)(p * 16 + dof) * 2);
                uint32_t t[4];
                ldsm4t(vb + off, t);
                vh[2*p][0]=t[0]; vh[2*p][1]=t[1]; vh[2*p+1][0]=t[2]; vh[2*p+1][1]=t[3];
                ldsm4t(vb + 4096 + off, t);
                vl[2*p][0]=t[0]; vl[2*p][1]=t[1]; vl[2*p+1][0]=t[2]; vl[2*p+1][1]=t[3];
            }
#pragma unroll
            for (int nt = 0; nt < 8; nt++) {
                mma16816(accv[nt], sah[ks], vh[nt]);
                mma16816(accv[nt], sah[ks], vl[nt]);
                mma16816(accv[nt], sal[ks], vh[nt]);
            }
        }
    }

    // rowsum finalize: quad-reduce, each row owned by exactly one warp
    rs0 += __shfl_xor_sync(0xFFFFFFFFu, rs0, 1);
    rs0 += __shfl_xor_sync(0xFFFFFFFFu, rs0, 2);
    rs1 += __shfl_xor_sync(0xFFFFFFFFu, rs1, 1);
    rs1 += __shfl_xor_sync(0xFFFFFFFFu, rs1, 2);
    if ((lane & 3) == 0) {
        rsacc[wm + (lane >> 2)]     = rs0;
        rsacc[wm + 8 + (lane >> 2)] = rs1;
    }
    __syncthreads();
    if (tid < 128) invp[tid] = 1.f / rsacc[tid];
    cp_wait<0>();
    __syncthreads();

    // ---- vals epilogue: scale by inv, pack hi/lo, store ----
    {
        __nv_bfloat16* Oh = voh + (size_t)z * Sc * HDc + (size_t)(qt * 128) * HDc;
        __nv_bfloat16* Ol = vol + (size_t)z * Sc * HDc + (size_t)(qt * 128) * HDc;
        const int r0 = wm + (lane >> 2);
        const float i0 = invp[r0], i1 = invp[r0 + 8];
        const int ccb = (lane & 3) * 2;
#pragma unroll
        for (int nt = 0; nt < 8; nt++) {
            const int cc = ccb + nt * 8;
            uint32_t hh, ll;
            pack_hilo(accv[nt][0] * i0, accv[nt][1] * i0, hh, ll);
            *reinterpret_cast<uint32_t*>(Oh + (size_t)r0 * HDc + cc) = hh;
            *reinterpret_cast<uint32_t*>(Ol + (size_t)r0 * HDc + cc) = ll;
            pack_hilo(accv[nt][2] * i1, accv[nt][3] * i1, hh, ll);
            *reinterpret_cast<uint32_t*>(Oh + (size_t)(r0 + 8) * HDc + cc) = hh;
            *reinterpret_cast<uint32_t*>(Ol + (size_t)(r0 + 8) * HDc + cc) = ll;
        }
    }

    // ---- pass 2: recompute QK in 64-row chunks, write normalized attn ----
    const int wm2 = (w & 3) * 32, wnq2 = (w >> 2) * 32;
#pragma unroll
    for (int s = 0; s < 2; s++) {
        const uint32_t kb = sb0 + FA_K + (uint32_t)s * 16384;
#pragma unroll
        for (int i = 0; i < 2; i++) {
            const int id = tid + 256 * i;
            const int row = id >> 3, c16 = id & 7;
            const uint32_t d = sw128((uint32_t)row * 128 + c16 * 16);
            const size_t so = (size_t)(s * 64 + row) * TD3 + c16 * 8;
            cp16(kb + d,        Kgh + so);
            cp16(kb + 8192 + d, Kgl + so);
        }
        cp_commit();
    }
#pragma unroll 1
    for (int c = 0; c < 32; c++) {
        cp_wait<1>();
        __syncthreads();
        float aq[2][4][4] = {};
        computeQK64(sb0, sb0 + FA_K + (uint32_t)(c % 3) * 16384, wm2, wnq2, lane, aq);
        if (c + 2 < 32) {
            const uint32_t kb = sb0 + FA_K + (uint32_t)((c + 2) % 3) * 16384;
#pragma unroll
            for (int i = 0; i < 2; i++) {
                const int id = tid + 256 * i;
                const int row = id >> 3, c16 = id & 7;
                const uint32_t d = sw128((uint32_t)row * 128 + c16 * 16);
                const size_t so = (size_t)((c + 2) * 64 + row) * TD3 + c16 * 8;
                cp16(kb + d,        Kgh + so);
                cp16(kb + 8192 + d, Kgl + so);
            }
        }
        cp_commit();
#pragma unroll
        for (int mt = 0; mt < 2; mt++) {
            const int r = wm2 + mt * 16 + (lane >> 2);
            const float i0 = invp[r], i1 = invp[r + 8];
#pragma unroll
            for (int nt = 0; nt < 4; nt++) {
                const int col = c * 64 + wnq2 + nt * 8 + (lane & 3) * 2;
                float2 v0 = {fexp8(aq[mt][nt][0]) * i0, fexp8(aq[mt][nt][1]) * i0};
                float2 v1 = {fexp8(aq[mt][nt][2]) * i1, fexp8(aq[mt][nt][3]) * i1};
                *reinterpret_cast<float2*>(Az + (size_t)r * Sc + col) = v0;
                *reinterpret_cast<float2*>(Az + (size_t)(r + 8) * Sc + col) = v1;
            }
        }
    }
}

// ---------------------------------------------------------------------------
extern "C" void kernel_launch(void* const* d_in, const int* in_sizes, int n_in,
                              void* d_out, int out_size)
{
    const float* x     = (const float*)d_in[0];
    const float* w_qkv = (const float*)d_in[1];
    const float* b_qkv = (const float*)d_in[2];
    const float* w_out = (const float*)d_in[3];
    const float* b_out = (const float*)d_in[4];
    float* out = (float*)d_out;

    const size_t BSD  = (size_t)Bc * Sc * Dc;
    const size_t BHSS = (size_t)Bc * Hc * Sc * Sc;

    float* attn_fb;
    cudaGetSymbolAddress((void**)&attn_fb, g_attn_fb);
    __nv_bfloat16 *xh, *xl, *wqh, *wql, *woh, *wol, *qkvh, *qkvl, *vh, *vl;
    cudaGetSymbolAddress((void**)&xh,   g_x_hi);   cudaGetSymbolAddress((void**)&xl,   g_x_lo);
    cudaGetSymbolAddress((void**)&wqh,  g_wq_hi);  cudaGetSymbolAddress((void**)&wql,  g_wq_lo);
    cudaGetSymbolAddress((void**)&woh,  g_wo_hi);  cudaGetSymbolAddress((void**)&wol,  g_wo_lo);
    cudaGetSymbolAddress((void**)&qkvh, g_qkv_hi); cudaGetSymbolAddress((void**)&qkvl, g_qkv_lo);
    cudaGetSymbolAddress((void**)&vh,   g_v_hi);   cudaGetSymbolAddress((void**)&vl,   g_v_lo);

    float* attn = ((size_t)out_size >= BSD + BHSS) ? (out + BSD) : attn_fb;

    cudaFuncSetAttribute(gemm_bf16<true>,  cudaFuncAttributeMaxDynamicSharedMemorySize, 98304);
    cudaFuncSetAttribute(gemm_bf16<false>, cudaFuncAttributeMaxDynamicSharedMemorySize, 98304);
    cudaFuncSetAttribute(fused_attn,       cudaFuncAttributeMaxDynamicSharedMemorySize, FA_SMEM);

    // 0) pre-split fp32 -> bf16 hi/lo
    cvt_hilo3<<<12288, 256>>>(
        (const float4*)x,     (uint2*)xh,  (uint2*)xl,
        (const float4*)w_qkv, (uint2*)wqh, (uint2*)wql,
        (const float4*)w_out, (uint2*)woh, (uint2*)wol);

    // 1) fused QKV projection -> bf16 hi/lo qkv
    gemm_bf16<true><<<dim3(TD3 / 128, Mrows / 128), 256, 98304>>>(
        xh, xl, wqh, wql, Dc, nullptr, qkvh, qkvl, TD3, b_qkv);

    // 2) fused attention: scores+softmax+PV in one kernel; attn written once
    fused_attn<<<dim3(Sc / 128, Bc * Hc), 256, FA_SMEM>>>(qkvh, qkvl, attn, vh, vl);

    // 3) output projection
    gemm_bf16<false><<<dim3(Dc / 128, Mrows / 128), 256, 98304>>>(
        vh, vl, woh, wol, Dc, out, nullptr, nullptr, Dc, b_out);
}

// round 16
// speedup vs baseline: 1.1348x; 1.0194x over previous
#include <cuda_runtime.h>
#include <cuda_bf16.h>
#include <cstdint>

// Problem constants
constexpr int Bc  = 4;
constexpr int Sc  = 2048;
constexpr int Dc  = 1024;
constexpr int Hc  = 16;
constexpr int HDc = 64;
constexpr int TD3 = 3 * Dc;          // 3072
constexpr int Mrows = Bc * Sc;       // 8192

// Scratch (device globals; no allocation in kernel_launch)
__device__ float g_attn_fb[(size_t)Bc * Hc * Sc * Sc];
__device__ __nv_bfloat16 g_x_hi[(size_t)Mrows * Dc],   g_x_lo[(size_t)Mrows * Dc];
__device__ __nv_bfloat16 g_wq_hi[(size_t)TD3 * Dc],    g_wq_lo[(size_t)TD3 * Dc];
__device__ __nv_bfloat16 g_wo_hi[(size_t)Dc * Dc],     g_wo_lo[(size_t)Dc * Dc];
__device__ __nv_bfloat16 g_qkv_hi[(size_t)Mrows * TD3], g_qkv_lo[(size_t)Mrows * TD3];
__device__ __nv_bfloat16 g_v_hi[(size_t)Mrows * Dc],   g_v_lo[(size_t)Mrows * Dc];

// ---------------------------------------------------------------------------
// helpers
// ---------------------------------------------------------------------------
__device__ __forceinline__ uint32_t smem_u32(const void* p) {
    uint32_t a;
    asm("{ .reg .u64 t; cvta.to.shared.u64 t, %1; cvt.u32.u64 %0, t; }"
        : "=r"(a) : "l"(p));
    return a;
}
__device__ __forceinline__ uint32_t sw64(uint32_t o)  { return o ^ ((o >> 3) & 0x30); }
__device__ __forceinline__ uint32_t sw128(uint32_t o) { return o ^ ((o >> 3) & 0x70); }

__device__ __forceinline__ void ldsm4(uint32_t a, uint32_t r[4]) {
    asm volatile("ldmatrix.sync.aligned.m8n8.x4.shared.b16 {%0,%1,%2,%3}, [%4];"
                 : "=r"(r[0]), "=r"(r[1]), "=r"(r[2]), "=r"(r[3]) : "r"(a));
}
__device__ __forceinline__ void ldsm4t(uint32_t a, uint32_t r[4]) {
    asm volatile("ldmatrix.sync.aligned.m8n8.x4.trans.shared.b16 {%0,%1,%2,%3}, [%4];"
                 : "=r"(r[0]), "=r"(r[1]), "=r"(r[2]), "=r"(r[3]) : "r"(a));
}
__device__ __forceinline__ void mma16816(float d[4], const uint32_t a[4], const uint32_t b[2]) {
    asm volatile(
        "mma.sync.aligned.m16n8k16.row.col.f32.bf16.bf16.f32 "
        "{%0,%1,%2,%3}, {%4,%5,%6,%7}, {%8,%9}, {%0,%1,%2,%3};"
        : "+f"(d[0]), "+f"(d[1]), "+f"(d[2]), "+f"(d[3])
        : "r"(a[0]), "r"(a[1]), "r"(a[2]), "r"(a[3]), "r"(b[0]), "r"(b[1]));
}
__device__ __forceinline__ void cp16(uint32_t dst, const void* src) {
    asm volatile("cp.async.cg.shared.global [%0], [%1], 16;" :: "r"(dst), "l"(src));
}
__device__ __forceinline__ void cp_commit() {
    asm volatile("cp.async.commit_group;" ::: "memory");
}
template <int N> __device__ __forceinline__ void cp_wait() {
    asm volatile("cp.async.wait_group %0;" :: "n"(N) : "memory");
}
__device__ __forceinline__ void split_hilo(float4 v, uint2& hw, uint2& lw) {
    __nv_bfloat162 h01 = __floats2bfloat162_rn(v.x, v.y);
    __nv_bfloat162 h23 = __floats2bfloat162_rn(v.z, v.w);
    float r0 = v.x - __low2float(h01);
    float r1 = v.y - __high2float(h01);
    float r2 = v.z - __low2float(h23);
    float r3 = v.w - __high2float(h23);
    __nv_bfloat162 l01 = __floats2bfloat162_rn(r0, r1);
    __nv_bfloat162 l23 = __floats2bfloat162_rn(r2, r3);
    hw.x = *reinterpret_cast<uint32_t*>(&h01); hw.y = *reinterpret_cast<uint32_t*>(&h23);
    lw.x = *reinterpret_cast<uint32_t*>(&l01); lw.y = *reinterpret_cast<uint32_t*>(&l23);
}
__device__ __forceinline__ void pack_hilo(float v0, float v1, uint32_t& h, uint32_t& l) {
    __nv_bfloat162 h2 = __floats2bfloat162_rn(v0, v1);
    float r0 = v0 - __low2float(h2), r1 = v1 - __high2float(h2);
    __nv_bfloat162 l2 = __floats2bfloat162_rn(r0, r1);
    h = *reinterpret_cast<uint32_t*>(&h2);
    l = *reinterpret_cast<uint32_t*>(&l2);
}
// exp(s/8) via 2^(s*0.125*log2e), degree-6 poly + exponent splice (FMA pipe).
__device__ __forceinline__ float fexp8(float s) {
    float v = s * 0.1803368801111244f;   // 0.125 * log2(e)
    float fl = floorf(v);
    float f = v - fl;
    float p = 1.5435906e-4f;
    p = fmaf(p, f, 1.3333558e-3f);
    p = fmaf(p, f, 9.6181291e-3f);
    p = fmaf(p, f, 5.5504109e-2f);
    p = fmaf(p, f, 2.4022651e-1f);
    p = fmaf(p, f, 6.9314718e-1f);
    p = fmaf(p, f, 1.0f);
    return __int_as_float(__float_as_int(p) + ((int)fl << 23));
}

// ---------------------------------------------------------------------------
// merged convert kernel: three fp32 -> (hi, lo) arrays in one launch
// ---------------------------------------------------------------------------
__global__ __launch_bounds__(256) void cvt_hilo3(
    const float4* __restrict__ in0, uint2* __restrict__ h0, uint2* __restrict__ l0,
    const float4* __restrict__ in1, uint2* __restrict__ h1, uint2* __restrict__ l1,
    const float4* __restrict__ in2, uint2* __restrict__ h2, uint2* __restrict__ l2)
{
    const int bx = blockIdx.x;
    const float4* in; uint2 *hp, *lp; int i;
    if (bx < 8192)       { in = in0; hp = h0; lp = l0; i = bx * 256 + threadIdx.x; }
    else if (bx < 11264) { in = in1; hp = h1; lp = l1; i = (bx - 8192) * 256 + threadIdx.x; }
    else                 { in = in2; hp = h2; lp = l2; i = (bx - 11264) * 256 + threadIdx.x; }
    uint2 h, l;
    split_hilo(in[i], h, l);
    hp[i] = h; lp[i] = l;
}

// ---------------------------------------------------------------------------
// GEMM compute core: one BK=32 chunk; A,B tiles 128 rows x 64B, SW64
// ---------------------------------------------------------------------------
__device__ __forceinline__ void compute64(uint32_t sb, int wm, int wn, int lane,
                                          float acc[2][8][4]) {
    const uint32_t Ah = sb, Al = sb + 8192, Bh = sb + 16384, Bl = sb + 24576;
    const int arow = ((lane >> 3) & 1) * 8 + (lane & 7);
    const int brow = ((lane >> 4) & 1) * 8 + (lane & 7);
#pragma unroll
    for (int ks = 0; ks < 2; ks++) {
        const uint32_t akb = (uint32_t)(ks * 32 + ((lane >> 4) & 1) * 16);
        const uint32_t bkb = (uint32_t)(ks * 32 + ((lane >> 3) & 1) * 16);
        uint32_t ah[2][4], al[2][4];
#pragma unroll
        for (int mt = 0; mt < 2; mt++) {
            const uint32_t off = sw64((uint32_t)(wm + mt * 16 + arow) * 64 + akb);
            ldsm4(Ah + off, ah[mt]);
            ldsm4(Al + off, al[mt]);
        }
#pragma unroll
        for (int half = 0; half < 2; half++) {
            uint32_t bh[4][2], bl[4][2];
#pragma unroll
            for (int p = 0; p < 2; p++) {
                const uint32_t off = sw64((uint32_t)(wn + (half * 2 + p) * 16 + brow) * 64 + bkb);
                uint32_t t[4];
                ldsm4(Bh + off, t);
                bh[2*p][0]=t[0]; bh[2*p][1]=t[1]; bh[2*p+1][0]=t[2]; bh[2*p+1][1]=t[3];
                ldsm4(Bl + off, t);
                bl[2*p][0]=t[0]; bl[2*p][1]=t[1]; bl[2*p+1][0]=t[2]; bl[2*p+1][1]=t[3];
            }
#pragma unroll
            for (int nt = 0; nt < 4; nt++)
#pragma unroll
                for (int mt = 0; mt < 2; mt++) {
                    mma16816(acc[mt][half*4+nt], ah[mt], bh[nt]);
                    mma16816(acc[mt][half*4+nt], ah[mt], bl[nt]);
                    mma16816(acc[mt][half*4+nt], al[mt], bh[nt]);
                }
        }
    }
}

// cp.async one 128x32 bf16 tile (8KB), SW64 rows
__device__ __forceinline__ void cp_tile(uint32_t dst_base, const __nv_bfloat16* __restrict__ src,
                                        int K, int k0, int tid)
{
#pragma unroll
    for (int i = 0; i < 2; i++) {
        const int id = tid + 256 * i;
        const int row = id >> 2, c16 = id & 3;
        cp16(dst_base + sw64((uint32_t)row * 64 + c16 * 16),
             src + (size_t)row * K + k0 + c16 * 8);
    }
}

// ---------------------------------------------------------------------------
// GEMM: C[128x128] = A @ B^T + bias; 3-stage cp.async, 2 CTAs/SM
// ---------------------------------------------------------------------------
template <bool BF16OUT>
__global__ __launch_bounds__(256, 2) void gemm_bf16(
    const __nv_bfloat16* __restrict__ Ahg, const __nv_bfloat16* __restrict__ Alg,
    const __nv_bfloat16* __restrict__ Bhg, const __nv_bfloat16* __restrict__ Blg,
    int K, float* __restrict__ C, __nv_bfloat16* __restrict__ Chi,
    __nv_bfloat16* __restrict__ Clo, int N, const float* __restrict__ bias)
{
    extern __shared__ uint8_t sm[];
    const uint32_t sb0 = smem_u32(sm);
    const int tid = threadIdx.x, lane = tid & 31, w = tid >> 5;
    const int wm = (w & 3) * 32, wn = (w >> 2) * 64;

    Ahg += (size_t)(blockIdx.y * 128) * K;
    Alg += (size_t)(blockIdx.y * 128) * K;
    Bhg += (size_t)(blockIdx.x * 128) * K;
    Blg += (size_t)(blockIdx.x * 128) * K;

    const int NC = K >> 5;
#pragma unroll 1
    for (int s = 0; s < 2; s++) {
        const uint32_t st = sb0 + (uint32_t)s * 32768;
        cp_tile(st,          Ahg, K, s * 32, tid);
        cp_tile(st + 8192,   Alg, K, s * 32, tid);
        cp_tile(st + 16384,  Bhg, K, s * 32, tid);
        cp_tile(st + 24576,  Blg, K, s * 32, tid);
        cp_commit();
    }

    float acc[2][8][4] = {};
#pragma unroll 1
    for (int c = 0; c < NC; c++) {
        cp_wait<1>();
        __syncthreads();
        if (c + 2 < NC) {
            const uint32_t st = sb0 + (uint32_t)((c + 2) % 3) * 32768;
            cp_tile(st,          Ahg, K, (c + 2) * 32, tid);
            cp_tile(st + 8192,   Alg, K, (c + 2) * 32, tid);
            cp_tile(st + 16384,  Bhg, K, (c + 2) * 32, tid);
            cp_tile(st + 24576,  Blg, K, (c + 2) * 32, tid);
        }
        cp_commit();
        compute64(sb0 + (uint32_t)(c % 3) * 32768, wm, wn, lane, acc);
    }

    const int gr = blockIdx.y * 128 + wm + (lane >> 2);
    const int gc = blockIdx.x * 128 + wn + (lane & 3) * 2;
#pragma unroll
    for (int mt = 0; mt < 2; mt++) {
        const int r0 = gr + mt * 16;
#pragma unroll
        for (int nt = 0; nt < 8; nt++) {
            const int cc = gc + nt * 8;
            const float b0 = __ldg(bias + cc), b1 = __ldg(bias + cc + 1);
            const float v00 = acc[mt][nt][0] + b0, v01 = acc[mt][nt][1] + b1;
            const float v10 = acc[mt][nt][2] + b0, v11 = acc[mt][nt][3] + b1;
            if (BF16OUT) {
                uint32_t h, l;
                pack_hilo(v00, v01, h, l);
                *reinterpret_cast<uint32_t*>(Chi + (size_t)r0 * N + cc) = h;
                *reinterpret_cast<uint32_t*>(Clo + (size_t)r0 * N + cc) = l;
                pack_hilo(v10, v11, h, l);
                *reinterpret_cast<uint32_t*>(Chi + (size_t)(r0 + 8) * N + cc) = h;
                *reinterpret_cast<uint32_t*>(Clo + (size_t)(r0 + 8) * N + cc) = l;
            } else {
                float2 u0 = {v00, v01}, u1 = {v10, v11};
                *reinterpret_cast<float2*>(C + (size_t)r0 * N + cc) = u0;
                *reinterpret_cast<float2*>(C + (size_t)(r0 + 8) * N + cc) = u1;
            }
        }
    }
}

// ---------------------------------------------------------------------------
// Fused attention.
// Pass 1 (row-split warps, register S): 4-stage K+V ring, 2 chunks per sync.
//   Prefetch targets = stages computed LAST iteration (barrier-protected).
// Pass 2 (64-row kv chunks): 4-stage ring, 2 chunks per sync; writes attn once.
// smem layout (bytes):
//   Qh @0 (16K), Ql @16384 (16K)
//   KV stages 4 x 16K @32768 (pass1: Kh 4K, Kl 4K, Vh 4K, Vl 4K per stage)
//                              (pass2: K64 stage = Kh 8K, Kl 8K)
//   rsacc[128] f32 @98304 ; inv[128] f32 @98816
// ---------------------------------------------------------------------------
constexpr uint32_t FA_Q   = 0;
constexpr uint32_t FA_KV  = 32768;
constexpr uint32_t FA_RS  = 98304;
constexpr uint32_t FA_INV = 98816;
constexpr uint32_t FA_SMEM = 99328;

// QK chunk (warp tile 16 rows x 32 kv): 4 n8 C-frags, 3-term bf16
__device__ __forceinline__ void computeQK16(uint32_t sb0, uint32_t kb, int wm,
                                            int lane, float aq[4][4]) {
    const uint32_t Qh = sb0 + FA_Q, Ql = sb0 + FA_Q + 16384;
    const uint32_t Kh = kb, Kl = kb + 4096;
    const int arow = ((lane >> 3) & 1) * 8 + (lane & 7);
    const int brow = ((lane >> 4) & 1) * 8 + (lane & 7);
#pragma unroll
    for (int ks = 0; ks < 4; ks++) {
        const uint32_t akb = (uint32_t)(ks * 32 + ((lane >> 4) & 1) * 16);
        const uint32_t bkb = (uint32_t)(ks * 32 + ((lane >> 3) & 1) * 16);
        uint32_t qh[4], ql_[4];
        const uint32_t aoff = sw128((uint32_t)(wm + arow) * 128 + akb);
        ldsm4(Qh + aoff, qh);
        ldsm4(Ql + aoff, ql_);
        uint32_t bh[4][2], bl[4][2];
#pragma unroll
        for (int p = 0; p < 2; p++) {
            uint32_t t[4];
            const uint32_t boff = sw128((uint32_t)(p * 16 + brow) * 128 + bkb);
            ldsm4(Kh + boff, t);
            bh[2*p][0]=t[0]; bh[2*p][1]=t[1]; bh[2*p+1][0]=t[2]; bh[2*p+1][1]=t[3];
            ldsm4(Kl + boff, t);
            bl[2*p][0]=t[0]; bl[2*p][1]=t[1]; bl[2*p+1][0]=t[2]; bl[2*p+1][1]=t[3];
        }
#pragma unroll
        for (int nt = 0; nt < 4; nt++) {
            mma16816(aq[nt], qh, bh[nt]);
            mma16816(aq[nt], qh, bl[nt]);
            mma16816(aq[nt], ql_, bh[nt]);
        }
    }
}

// QK chunk (64 rows): warp tile 32x32; K stage = 16K (hi 8K, lo 8K)
__device__ __forceinline__ void computeQK64(uint32_t sb0, uint32_t kb, int wm2, int wnq2,
                                            int lane, float aq[2][4][4]) {
    const uint32_t Qh = sb0 + FA_Q, Ql = sb0 + FA_Q + 16384;
    const uint32_t Kh = kb, Kl = kb + 8192;
    const int arow = ((lane >> 3) & 1) * 8 + (lane & 7);
    const int brow = ((lane >> 4) & 1) * 8 + (lane & 7);
#pragma unroll
    for (int ks = 0; ks < 4; ks++) {
        const uint32_t akb = (uint32_t)(ks * 32 + ((lane >> 4) & 1) * 16);
        const uint32_t bkb = (uint32_t)(ks * 32 + ((lane >> 3) & 1) * 16);
        uint32_t qh[2][4], ql_[2][4];
#pragma unroll
        for (int mt = 0; mt < 2; mt++) {
            const uint32_t off = sw128((uint32_t)(wm2 + mt * 16 + arow) * 128 + akb);
            ldsm4(Qh + off, qh[mt]);
            ldsm4(Ql + off, ql_[mt]);
        }
        uint32_t bh[4][2], bl[4][2];
#pragma unroll
        for (int p = 0; p < 2; p++) {
            uint32_t t[4];
            const uint32_t boff = sw128((uint32_t)(wnq2 + p * 16 + brow) * 128 + bkb);
            ldsm4(Kh + boff, t);
            bh[2*p][0]=t[0]; bh[2*p][1]=t[1]; bh[2*p+1][0]=t[2]; bh[2*p+1][1]=t[3];
            ldsm4(Kl + boff, t);
            bl[2*p][0]=t[0]; bl[2*p][1]=t[1]; bl[2*p+1][0]=t[2]; bl[2*p+1][1]=t[3];
        }
#pragma unroll
        for (int nt = 0; nt < 4; nt++)
#pragma unroll
            for (int mt = 0; mt < 2; mt++) {
                mma16816(aq[mt][nt], qh[mt], bh[nt]);
                mma16816(aq[mt][nt], qh[mt], bl[nt]);
                mma16816(aq[mt][nt], ql_[mt], bh[nt]);
            }
    }
}

__global__ __launch_bounds__(256, 2) void fused_attn(
    const __nv_bfloat16* __restrict__ qkh, const __nv_bfloat16* __restrict__ qkl,
    float* __restrict__ attn_out,
    __nv_bfloat16* __restrict__ voh, __nv_bfloat16* __restrict__ vol)
{
    extern __shared__ uint8_t sm[];
    const uint32_t sb0 = smem_u32(sm);
    float* rsacc = reinterpret_cast<float*>(sm + FA_RS);
    float* invp  = reinterpret_cast<float*>(sm + FA_INV);
    const int tid = threadIdx.x, lane = tid & 31, w = tid >> 5;
    const int wm = w * 16;           // pass1: each warp owns 16 q-rows

    const int qt = blockIdx.x, z = blockIdx.y, b = z >> 4, h = z & 15;
    const size_t hb = (size_t)b * Sc * TD3 + h * 192;
    const __nv_bfloat16* Qgh = qkh + hb + (size_t)(qt * 128) * TD3;
    const __nv_bfloat16* Qgl = qkl + hb + (size_t)(qt * 128) * TD3;
    const __nv_bfloat16* Kgh = qkh + hb + 64;
    const __nv_bfloat16* Kgl = qkl + hb + 64;
    const __nv_bfloat16* Vgh = qkh + hb + 128;
    const __nv_bfloat16* Vgl = qkl + hb + 128;
    float* Az = attn_out + (size_t)z * Sc * Sc + (size_t)(qt * 128) * Sc;

    const int krow = tid >> 3, kc16 = tid & 7;               // 32-row chunk loads
    const uint32_t kdst = sw128((uint32_t)krow * 128 + kc16 * 16);

    // prologue: Q + chunks 0,1 of K,V
#pragma unroll
    for (int i = 0; i < 4; i++) {
        const int id = tid + 256 * i;
        const int row = id >> 3, c16 = id & 7;
        const uint32_t d = sw128((uint32_t)row * 128 + c16 * 16);
        const size_t so = (size_t)row * TD3 + c16 * 8;
        cp16(sb0 + FA_Q + d,         Qgh + so);
        cp16(sb0 + FA_Q + 16384 + d, Qgl + so);
    }
#pragma unroll
    for (int s = 0; s < 2; s++) {
        const size_t so = (size_t)(s * 32 + krow) * TD3 + kc16 * 8;
        const uint32_t st = sb0 + FA_KV + (uint32_t)s * 16384;
        cp16(st +         kdst, Kgh + so);
        cp16(st +  4096 + kdst, Kgl + so);
        cp16(st +  8192 + kdst, Vgh + so);
        cp16(st + 12288 + kdst, Vgl + so);
        cp_commit();
    }

    // ---- pass 1: 2 chunks per sync; QK C-frags -> exp -> A-frags -> PV ----
    float accv[8][4] = {};
    float rs0 = 0.f, rs1 = 0.f;
    const int krw = ((lane >> 3) & 1) * 8 + (lane & 7);   // V ldsm4t row pattern
    const int dof = ((lane >> 4) & 1) * 8;
#pragma unroll 1
    for (int c = 0; c < 64; c += 2) {
        cp_wait<0>();
        __syncthreads();
        // prefetch chunks c+2, c+3 into stages (c+2)%4, (c+3)%4
        //  (= stages of chunks c-2, c-1: computed last iter, barrier-protected)
        if (c + 2 < 64) {
#pragma unroll
            for (int j = 0; j < 2; j++) {
                const int cc = c + 2 + j;
                const size_t so = (size_t)(cc * 32 + krow) * TD3 + kc16 * 8;
                const uint32_t st = sb0 + FA_KV + (uint32_t)(cc & 3) * 16384;
                cp16(st +         kdst, Kgh + so);
                cp16(st +  4096 + kdst, Kgl + so);
                cp16(st +  8192 + kdst, Vgh + so);
                cp16(st + 12288 + kdst, Vgl + so);
                cp_commit();
            }
        }
#pragma unroll
        for (int hh = 0; hh < 2; hh++) {
            const uint32_t st = sb0 + FA_KV + (uint32_t)((c + hh) & 3) * 16384;
            float aq[4][4] = {};
            computeQK16(sb0, st, wm, lane, aq);
            // exp + pack into PV A-frags (hi/lo); rowsums in regs
            uint32_t sah[2][4], sal[2][4];
#pragma unroll
            for (int nt = 0; nt < 4; nt++) {
                const float e0 = fexp8(aq[nt][0]);
                const float e1 = fexp8(aq[nt][1]);
                const float e2 = fexp8(aq[nt][2]);
                const float e3 = fexp8(aq[nt][3]);
                rs0 += e0 + e1;
                rs1 += e2 + e3;
                const int f = nt >> 1, half = nt & 1;
                pack_hilo(e0, e1, sah[f][half * 2],     sal[f][half * 2]);
                pack_hilo(e2, e3, sah[f][half * 2 + 1], sal[f][half * 2 + 1]);
            }
            // PV: O[16x64] += Sfrag(16x32) @ V(32x64)
            const uint32_t vb = st + 8192;
#pragma unroll
            for (int ks = 0; ks < 2; ks++) {
                uint32_t vh[8][2], vl[8][2];
#pragma unroll
                for (int p = 0; p < 4; p++) {
                    const uint32_t off = sw128((uint32_t)(ks * 16 + krw) * 128 +
                                               (uint32_t)(p * 16 + dof) * 2);
                    uint32_t t[4];
                    ldsm4t(vb + off, t);
                    vh[2*p][0]=t[0]; vh[2*p][1]=t[1]; vh[2*p+1][0]=t[2]; vh[2*p+1][1]=t[3];
                    ldsm4t(vb + 4096 + off, t);
                    vl[2*p][0]=t[0]; vl[2*p][1]=t[1]; vl[2*p+1][0]=t[2]; vl[2*p+1][1]=t[3];
                }
#pragma unroll
                for (int nt = 0; nt < 8; nt++) {
                    mma16816(accv[nt], sah[ks], vh[nt]);
                    mma16816(accv[nt], sah[ks], vl[nt]);
                    mma16816(accv[nt], sal[ks], vh[nt]);
                }
            }
        }
    }

    // rowsum finalize: quad-reduce, each row owned by exactly one warp
    rs0 += __shfl_xor_sync(0xFFFFFFFFu, rs0, 1);
    rs0 += __shfl_xor_sync(0xFFFFFFFFu, rs0, 2);
    rs1 += __shfl_xor_sync(0xFFFFFFFFu, rs1, 1);
    rs1 += __shfl_xor_sync(0xFFFFFFFFu, rs1, 2);
    if ((lane & 3) == 0) {
        rsacc[wm + (lane >> 2)]     = rs0;
        rsacc[wm + 8 + (lane >> 2)] = rs1;
    }
    __syncthreads();
    if (tid < 128) invp[tid] = 1.f / rsacc[tid];
    cp_wait<0>();
    __syncthreads();

    // ---- vals epilogue: scale by inv, pack hi/lo, store ----
    {
        __nv_bfloat16* Oh = voh + (size_t)z * Sc * HDc + (size_t)(qt * 128) * HDc;
        __nv_bfloat16* Ol = vol + (size_t)z * Sc * HDc + (size_t)(qt * 128) * HDc;
        const int r0 = wm + (lane >> 2);
        const float i0 = invp[r0], i1 = invp[r0 + 8];
        const int ccb = (lane & 3) * 2;
#pragma unroll
        for (int nt = 0; nt < 8; nt++) {
            const int cc = ccb + nt * 8;
            uint32_t hh, ll;
            pack_hilo(accv[nt][0] * i0, accv[nt][1] * i0, hh, ll);
            *reinterpret_cast<uint32_t*>(Oh + (size_t)r0 * HDc + cc) = hh;
            *reinterpret_cast<uint32_t*>(Ol + (size_t)r0 * HDc + cc) = ll;
            pack_hilo(accv[nt][2] * i1, accv[nt][3] * i1, hh, ll);
            *reinterpret_cast<uint32_t*>(Oh + (size_t)(r0 + 8) * HDc + cc) = hh;
            *reinterpret_cast<uint32_t*>(Ol + (size_t)(r0 + 8) * HDc + cc) = ll;
        }
    }

    // ---- pass 2: 64-row chunks, 2 per sync; write normalized attention ----
    const int wm2 = (w & 3) * 32, wnq2 = (w >> 2) * 32;
#pragma unroll
    for (int s = 0; s < 2; s++) {
        const uint32_t kb = sb0 + FA_KV + (uint32_t)s * 16384;
#pragma unroll
        for (int i = 0; i < 2; i++) {
            const int id = tid + 256 * i;
            const int row = id >> 3, c16 = id & 7;
            const uint32_t d = sw128((uint32_t)row * 128 + c16 * 16);
            const size_t so = (size_t)(s * 64 + row) * TD3 + c16 * 8;
            cp16(kb + d,        Kgh + so);
            cp16(kb + 8192 + d, Kgl + so);
        }
        cp_commit();
    }
#pragma unroll 1
    for (int c = 0; c < 32; c += 2) {
        cp_wait<0>();
        __syncthreads();
        if (c + 2 < 32) {
#pragma unroll
            for (int j = 0; j < 2; j++) {
                const int cc = c + 2 + j;
                const uint32_t kb = sb0 + FA_KV + (uint32_t)(cc & 3) * 16384;
#pragma unroll
                for (int i = 0; i < 2; i++) {
                    const int id = tid + 256 * i;
                    const int row = id >> 3, c16 = id & 7;
                    const uint32_t d = sw128((uint32_t)row * 128 + c16 * 16);
                    const size_t so = (size_t)(cc * 64 + row) * TD3 + c16 * 8;
                    cp16(kb + d,        Kgh + so);
                    cp16(kb + 8192 + d, Kgl + so);
                }
                cp_commit();
            }
        }
#pragma unroll
        for (int hh = 0; hh < 2; hh++) {
            float aq[2][4][4] = {};
            computeQK64(sb0, sb0 + FA_KV + (uint32_t)((c + hh) & 3) * 16384,
                        wm2, wnq2, lane, aq);
#pragma unroll
            for (int mt = 0; mt < 2; mt++) {
                const int r = wm2 + mt * 16 + (lane >> 2);
                const float i0 = invp[r], i1 = invp[r + 8];
#pragma unroll
                for (int nt = 0; nt < 4; nt++) {
                    const int col = (c + hh) * 64 + wnq2 + nt * 8 + (lane & 3) * 2;
                    float2 v0 = {fexp8(aq[mt][nt][0]) * i0, fexp8(aq[mt][nt][1]) * i0};
                    float2 v1 = {fexp8(aq[mt][nt][2]) * i1, fexp8(aq[mt][nt][3]) * i1};
                    *reinterpret_cast<float2*>(Az + (size_t)r * Sc + col) = v0;
                    *reinterpret_cast<float2*>(Az + (size_t)(r + 8) * Sc + col) = v1;
                }
            }
        }
    }
}

// ---------------------------------------------------------------------------
extern "C" void kernel_launch(void* const* d_in, const int* in_sizes, int n_in,
                              void* d_out, int out_size)
{
    const float* x     = (const float*)d_in[0];
    const float* w_qkv = (const float*)d_in[1];
    const float* b_qkv = (const float*)d_in[2];
    const float* w_out = (const float*)d_in[3];
    const float* b_out = (const float*)d_in[4];
    float* out = (float*)d_out;

    const size_t BSD  = (size_t)Bc * Sc * Dc;
    const size_t BHSS = (size_t)Bc * Hc * Sc * Sc;

    float* attn_fb;
    cudaGetSymbolAddress((void**)&attn_fb, g_attn_fb);
    __nv_bfloat16 *xh, *xl, *wqh, *wql, *woh, *wol, *qkvh, *qkvl, *vh, *vl;
    cudaGetSymbolAddress((void**)&xh,   g_x_hi);   cudaGetSymbolAddress((void**)&xl,   g_x_lo);
    cudaGetSymbolAddress((void**)&wqh,  g_wq_hi);  cudaGetSymbolAddress((void**)&wql,  g_wq_lo);
    cudaGetSymbolAddress((void**)&woh,  g_wo_hi);  cudaGetSymbolAddress((void**)&wol,  g_wo_lo);
    cudaGetSymbolAddress((void**)&qkvh, g_qkv_hi); cudaGetSymbolAddress((void**)&qkvl, g_qkv_lo);
    cudaGetSymbolAddress((void**)&vh,   g_v_hi);   cudaGetSymbolAddress((void**)&vl,   g_v_lo);

    float* attn = ((size_t)out_size >= BSD + BHSS) ? (out + BSD) : attn_fb;

    cudaFuncSetAttribute(gemm_bf16<true>,  cudaFuncAttributeMaxDynamicSharedMemorySize, 98304);
    cudaFuncSetAttribute(gemm_bf16<false>, cudaFuncAttributeMaxDynamicSharedMemorySize, 98304);
    cudaFuncSetAttribute(fused_attn,       cudaFuncAttributeMaxDynamicSharedMemorySize, FA_SMEM);

    // 0) pre-split fp32 -> bf16 hi/lo
    cvt_hilo3<<<12288, 256>>>(
        (const float4*)x,     (uint2*)xh,  (uint2*)xl,
        (const float4*)w_qkv, (uint2*)wqh, (uint2*)wql,
        (const float4*)w_out, (uint2*)woh, (uint2*)wol);

    // 1) fused QKV projection -> bf16 hi/lo qkv
    gemm_bf16<true><<<dim3(TD3 / 128, Mrows / 128), 256, 98304>>>(
        xh, xl, wqh, wql, Dc, nullptr, qkvh, qkvl, TD3, b_qkv);

    // 2) fused attention: scores+softmax+PV in one kernel; attn written once
    fused_attn<<<dim3(Sc / 128, Bc * Hc), 256, FA_SMEM>>>(qkvh, qkvl, attn, vh, vl);

    // 3) output projection
    gemm_bf16<false><<<dim3(Dc / 128, Mrows / 128), 256, 98304>>>(
        vh, vl, woh, wol, Dc, out, nullptr, nullptr, Dc, b_out);
}